// round 6
// baseline (speedup 1.0000x reference)
#include <cuda_runtime.h>
#include <cuda_bf16.h>
#include <math.h>

// Problem constants
#define AA 16
#define BB 16
#define SS 128
#define DD 512
#define NN 256        // A*B
#define LL 5
#define SC 132        // S + L - 1
#define HH 8
#define DK 64

// K-dim permutation (within each 8-group): pos = (i<4) ? 2i : 2(i-4)+1
// stored order: [k0,k4,k1,k5,k2,k6,k3,k7]

// ---------------- scratch (device globals; no runtime allocation) ----------------
__device__ unsigned g_xcq[(size_t)NN*SC*DD];   // tf32, K-permuted
__device__ unsigned g_xck[(size_t)NN*SC*DD];   // tf32, K-permuted
__device__ float    g_yq [(size_t)NN*SC*DD];
__device__ float    g_yk [(size_t)NN*SC*DD];
__device__ float    g_wq [(size_t)NN*SS*LL];
__device__ float    g_wk [(size_t)NN*SS*LL];
__device__ float    g_q  [(size_t)NN*SS*DD];
__device__ float    g_k  [(size_t)NN*SS*DD];
__device__ float    g_v  [(size_t)NN*SS*DD];
__device__ unsigned g_vtf[(size_t)NN*SS*DD];   // tf32 value, K-permuted
__device__ float    g_xa [(size_t)NN*SS*DD];   // [S,B,A,D]
__device__ unsigned g_xf [(size_t)NN*SS*DD];   // tf32 [A,B,S,D], K-permuted
__device__ unsigned g_Wt [4*(size_t)DD*DD];    // tf32 Wq,Wk,Wv,Wo, K-permuted

// ---------------- tf32 helpers ---------------------------------------------------
__device__ __forceinline__ unsigned f2tf32(float f) {
    unsigned u;
    asm("cvt.rna.tf32.f32 %0, %1;" : "=r"(u) : "f"(f));
    return u;
}

__device__ __forceinline__ void mma_tf32(float* d, const unsigned* a, const unsigned* b) {
    asm volatile(
        "mma.sync.aligned.m16n8k8.row.col.f32.tf32.tf32.f32 "
        "{%0,%1,%2,%3}, {%4,%5,%6,%7}, {%8,%9}, {%0,%1,%2,%3};"
        : "+f"(d[0]), "+f"(d[1]), "+f"(d[2]), "+f"(d[3])
        : "r"(a[0]), "r"(a[1]), "r"(a[2]), "r"(a[3]),
          "r"(b[0]), "r"(b[1]));
}

__device__ __forceinline__ void cp16(unsigned* smem_dst, const unsigned* gmem_src) {
    unsigned saddr = (unsigned)__cvta_generic_to_shared(smem_dst);
    asm volatile("cp.async.cg.shared.global [%0], [%1], 16;\n"
                 :: "r"(saddr), "l"(gmem_src));
}

// ---------------- elementwise f32 -> tf32, K-permuted ----------------------------
// thread handles one 8-element group
__global__ void k_cvt_perm(const float* __restrict__ src, unsigned* __restrict__ dst,
                           int n8) {
    int i = blockIdx.x * 256 + threadIdx.x;
    if (i < n8) {
        float4 v0 = ((const float4*)src)[2*i];
        float4 v1 = ((const float4*)src)[2*i + 1];
        uint4 u0 = make_uint4(f2tf32(v0.x), f2tf32(v1.x), f2tf32(v0.y), f2tf32(v1.y));
        uint4 u1 = make_uint4(f2tf32(v0.z), f2tf32(v1.z), f2tf32(v0.w), f2tf32(v1.w));
        ((uint4*)dst)[2*i]     = u0;
        ((uint4*)dst)[2*i + 1] = u1;
    }
}

// ---------------- concat pad + x -> xc [N,132,D] in tf32, K-permuted -------------
__global__ void k_concat_cvt(const float* __restrict__ x, const float* __restrict__ pad,
                             unsigned* __restrict__ xc) {
    int idx = blockIdx.x * 256 + threadIdx.x;     // 8-elem group index; total N*SC*64
    int c   = idx & 63;
    int row = idx >> 6;
    int n = row / SC;
    int s = row - n * SC;
    const float4* src;
    if (s < LL - 1)
        src = (const float4*)pad + ((size_t)n*(LL-1) + s)*128 + c*2;
    else
        src = (const float4*)x   + ((size_t)n*SS + (s - (LL-1)))*128 + c*2;
    float4 v0 = src[0];
    float4 v1 = src[1];
    uint4 u0 = make_uint4(f2tf32(v0.x), f2tf32(v1.x), f2tf32(v0.y), f2tf32(v1.y));
    uint4 u1 = make_uint4(f2tf32(v0.z), f2tf32(v1.z), f2tf32(v0.w), f2tf32(v1.w));
    ((uint4*)xc)[2*idx]     = u0;
    ((uint4*)xc)[2*idx + 1] = u1;
}

// ---------------- tf32 tensor-core GEMM, K-permuted inputs, LDS.64 fragments -----
// C[M,512] = A[M,512] @ W[512,512]^T + bias. A,W tf32-in-u32, K-permuted per 8.
// 128x128 block tile, BK=32, 2-stage cp.async, 256 threads (8 warps 4m x 2n),
// warp tile 32x64. Smem row stride 40 words (conflict-free LDS.64 per phase).
#define P_STRIDE 40
#define P_STG (128 * P_STRIDE)
__global__ void __launch_bounds__(256) gemm_p(const unsigned* __restrict__ A,
                                              const unsigned* __restrict__ W,
                                              const float* __restrict__ bias,
                                              float* __restrict__ C) {
    extern __shared__ unsigned sm[];   // [2 stages][As|Bs]
    int tid = threadIdx.x;
    int bm = blockIdx.y * 128;
    int bn = blockIdx.x * 128;
    int wid = tid >> 5, lane = tid & 31;
    int g = lane >> 2, tig = lane & 3;
    int wm = wid & 3, wn = wid >> 2;
    int m0 = wm * 32, n0 = wn * 64;

    const unsigned* Ab = A + (size_t)bm * 512;
    const unsigned* Wb = W + (size_t)bn * 512;

    float acc[2][8][4];
#pragma unroll
    for (int mt = 0; mt < 2; mt++)
#pragma unroll
        for (int nt = 0; nt < 8; nt++)
#pragma unroll
            for (int i = 0; i < 4; i++) acc[mt][nt][i] = 0.f;

#define PREFETCH(kt, stg)                                                         \
    {                                                                             \
        unsigned* sA = sm + (stg) * 2 * P_STG;                                    \
        unsigned* sB = sA + P_STG;                                                \
        _Pragma("unroll")                                                         \
        for (int i = 0; i < 4; i++) {                                             \
            int idx = tid + 256 * i;                                              \
            int r = idx >> 3, qd = idx & 7;                                       \
            cp16(sA + r * P_STRIDE + qd * 4, Ab + (size_t)r * 512 + (kt) + qd * 4); \
            cp16(sB + r * P_STRIDE + qd * 4, Wb + (size_t)r * 512 + (kt) + qd * 4); \
        }                                                                         \
        asm volatile("cp.async.commit_group;\n");                                 \
    }

    PREFETCH(0, 0);

#pragma unroll 1
    for (int kt = 0; kt < 512; kt += 32) {
        int stg = (kt >> 5) & 1;
        if (kt + 32 < 512) {
            PREFETCH(kt + 32, stg ^ 1);
            asm volatile("cp.async.wait_group 1;\n");
        } else {
            asm volatile("cp.async.wait_group 0;\n");
        }
        __syncthreads();

        const unsigned* As = sm + stg * 2 * P_STG;
        const unsigned* Bs = As + P_STG;
#pragma unroll
        for (int kc = 0; kc < 4; kc++) {
            int kb = kc * 8;
            // A fragments: LDS.64 pairs (a0,a2) and (a1,a3)
            uint2 alo[2], ahi[2];
#pragma unroll
            for (int mt = 0; mt < 2; mt++) {
                int row = m0 + mt * 16 + g;
                alo[mt] = *(const uint2*)&As[row * P_STRIDE + kb + 2 * tig];
                ahi[mt] = *(const uint2*)&As[(row + 8) * P_STRIDE + kb + 2 * tig];
            }
            uint2 bv[8];
#pragma unroll
            for (int nt = 0; nt < 8; nt++) {
                int col = n0 + nt * 8 + g;
                bv[nt] = *(const uint2*)&Bs[col * P_STRIDE + kb + 2 * tig];
            }
#pragma unroll
            for (int mt = 0; mt < 2; mt++) {
                unsigned af[4] = { alo[mt].x, ahi[mt].x, alo[mt].y, ahi[mt].y };
#pragma unroll
                for (int nt = 0; nt < 8; nt++) {
                    unsigned bf[2] = { bv[nt].x, bv[nt].y };
                    mma_tf32(acc[mt][nt], af, bf);
                }
            }
        }
        __syncthreads();
    }
#undef PREFETCH

#pragma unroll
    for (int mt = 0; mt < 2; mt++) {
        int row = bm + m0 + mt * 16 + g;
#pragma unroll
        for (int nt = 0; nt < 8; nt++) {
            int col = bn + n0 + nt * 8 + 2 * tig;
            float b0 = bias[col], b1 = bias[col + 1];
            float2 lo = make_float2(acc[mt][nt][0] + b0, acc[mt][nt][1] + b1);
            float2 hi = make_float2(acc[mt][nt][2] + b0, acc[mt][nt][3] + b1);
            *(float2*)&C[(size_t)row * 512 + col] = lo;
            *(float2*)&C[(size_t)(row + 8) * 512 + col] = hi;
        }
    }
}

// ---------------- local-window softmax weights: w[n,s,5] --------------------------
__global__ void k_weights(const float* __restrict__ y, float* __restrict__ w) {
    int gw = blockIdx.x * 4 + (threadIdx.x >> 5);   // warp -> (n,s)
    int lane = threadIdx.x & 31;
    int n = gw >> 7;
    int s = gw & 127;
    const float* base = y + (size_t)n * SC * DD;
    const float* cen  = base + (size_t)(s + LL - 1) * DD;
    float d0=0.f,d1=0.f,d2=0.f,d3=0.f,d4=0.f;
    for (int i = lane; i < DD; i += 32) {
        float cv = cen[i];
        d0 += cv * base[(s+0)*DD + i];
        d1 += cv * base[(s+1)*DD + i];
        d2 += cv * base[(s+2)*DD + i];
        d3 += cv * base[(s+3)*DD + i];
        d4 += cv * base[(s+4)*DD + i];
    }
#pragma unroll
    for (int off = 16; off; off >>= 1) {
        d0 += __shfl_xor_sync(0xffffffffu, d0, off);
        d1 += __shfl_xor_sync(0xffffffffu, d1, off);
        d2 += __shfl_xor_sync(0xffffffffu, d2, off);
        d3 += __shfl_xor_sync(0xffffffffu, d3, off);
        d4 += __shfl_xor_sync(0xffffffffu, d4, off);
    }
    if (lane == 0) {
        const float sc = 0.044194173824159216f;  // 1/sqrt(512)
        float s0 = d0*sc, s1 = d1*sc, s2 = d2*sc, s3 = d3*sc, s4 = d4*sc;
        float m = fmaxf(fmaxf(fmaxf(s0,s1), fmaxf(s2,s3)), s4);
        float e0 = __expf(s0-m), e1 = __expf(s1-m), e2 = __expf(s2-m),
              e3 = __expf(s3-m), e4 = __expf(s4-m);
        float inv = 1.f / (e0+e1+e2+e3+e4);
        float* wp = w + (size_t)gw * LL;
        wp[0]=e0*inv; wp[1]=e1*inv; wp[2]=e2*inv; wp[3]=e3*inv; wp[4]=e4*inv;
    }
}

// ---------------- scrambled-reshape gather ---------------------------------------
__global__ void k_gather(const float* __restrict__ y, const float* __restrict__ w,
                         float* __restrict__ out) {
    int ns = blockIdx.x;           // n*128 + s
    int n = ns >> 7;
    int s = ns & 127;
    float coef[LL];
    int   rowi[LL];
#pragma unroll
    for (int l = 0; l < LL; l++) {
        int f  = l * SS + s;
        int sp = f / 5;
        int lp = f - sp * 5;
        coef[l] = w[((size_t)n * SS + sp) * LL + lp];
        rowi[l] = sp + lp;
    }
    const float4* yb = (const float4*)y + (size_t)n * SC * 128;
    int c = threadIdx.x;   // 0..127 float4 lanes
    float4 acc = make_float4(0.f,0.f,0.f,0.f);
#pragma unroll
    for (int l = 0; l < LL; l++) {
        float4 v = yb[(size_t)rowi[l] * 128 + c];
        acc.x += coef[l]*v.x; acc.y += coef[l]*v.y;
        acc.z += coef[l]*v.z; acc.w += coef[l]*v.w;
    }
    ((float4*)out)[(size_t)ns * 128 + c] = acc;
}

// ---------------- attention 1 via tf32 MMA: per (n,h) block, S=128, dk=64 --------
// Writes output directly in [S,B,A,D] layout (fuses the x1->xa transpose).
#define Q_STR 68
#define V_STR 72
#define PS_STR 132
__global__ void __launch_bounds__(256) attn1_tc(const float* __restrict__ q,
                                                const float* __restrict__ k,
                                                const float* __restrict__ v,
                                                float* __restrict__ o) {
    extern __shared__ unsigned sm[];
    unsigned* Qs = sm;
    unsigned* Ks = sm + 128 * Q_STR;
    unsigned* Ps = sm;                       // overlay (valid after QK phase)
    unsigned* Vs = sm + 2 * 128 * Q_STR;
    float* inv_l = (float*)(Vs + 128 * V_STR);

    int n = blockIdx.x >> 3, h = blockIdx.x & 7;
    int tid = threadIdx.x;
    int lane = tid & 31;
    int g = lane >> 2, tig = lane & 3;
    int m0 = (tid >> 5) * 16;                // warp -> 16 rows

    // load Q,K,V head tiles, convert to tf32
#pragma unroll
    for (int i = 0; i < 8; i++) {
        int idx = tid + 256 * i;             // 0..2047
        int s = idx >> 4, dq = idx & 15;
        size_t goff = ((size_t)(n * 128 + s)) * 512 + h * 64 + dq * 4;
        float4 vq = *(const float4*)(q + goff);
        float4 vk = *(const float4*)(k + goff);
        float4 vv = *(const float4*)(v + goff);
        *(uint4*)&Qs[s * Q_STR + dq * 4] =
            make_uint4(f2tf32(vq.x), f2tf32(vq.y), f2tf32(vq.z), f2tf32(vq.w));
        *(uint4*)&Ks[s * Q_STR + dq * 4] =
            make_uint4(f2tf32(vk.x), f2tf32(vk.y), f2tf32(vk.z), f2tf32(vk.w));
        *(uint4*)&Vs[s * V_STR + dq * 4] =
            make_uint4(f2tf32(vv.x), f2tf32(vv.y), f2tf32(vv.z), f2tf32(vv.w));
    }
    __syncthreads();

    // scores = Q @ K^T  (warp: 16 rows x 128 cols)
    float acc[16][4];
#pragma unroll
    for (int nt = 0; nt < 16; nt++)
#pragma unroll
        for (int i = 0; i < 4; i++) acc[nt][i] = 0.f;

#pragma unroll
    for (int kc = 0; kc < 8; kc++) {
        int kb = kc * 8;
        unsigned af[4];
        af[0] = Qs[(m0 + g) * Q_STR + kb + tig];
        af[1] = Qs[(m0 + 8 + g) * Q_STR + kb + tig];
        af[2] = Qs[(m0 + g) * Q_STR + kb + tig + 4];
        af[3] = Qs[(m0 + 8 + g) * Q_STR + kb + tig + 4];
#pragma unroll
        for (int nt = 0; nt < 16; nt++) {
            unsigned bf[2];
            bf[0] = Ks[(nt * 8 + g) * Q_STR + kb + tig];
            bf[1] = Ks[(nt * 8 + g) * Q_STR + kb + tig + 4];
            mma_tf32(acc[nt], af, bf);
        }
    }
    __syncthreads();   // Q,K dead everywhere -> safe to overlay Ps

    float* Pf = (float*)Ps;
#pragma unroll
    for (int nt = 0; nt < 16; nt++) {
        int col = nt * 8 + 2 * tig;
        Pf[(m0 + g) * PS_STR + col]     = acc[nt][0];
        Pf[(m0 + g) * PS_STR + col + 1] = acc[nt][1];
        Pf[(m0 + 8 + g) * PS_STR + col]     = acc[nt][2];
        Pf[(m0 + 8 + g) * PS_STR + col + 1] = acc[nt][3];
    }
    __syncthreads();

    // softmax: 2 threads per row, exp stored tf32-rounded (unnormalized)
    {
        int r = tid >> 1;
        int halfc = (tid & 1) * 64;
        float* row = Pf + r * PS_STR + halfc;
        float mx = -1e30f;
#pragma unroll
        for (int j = 0; j < 64; j++) mx = fmaxf(mx, row[j]);
        mx = fmaxf(mx, __shfl_xor_sync(0xffffffffu, mx, 1));
        float mxs = mx * 0.125f;
        float sum = 0.f;
#pragma unroll
        for (int j = 0; j < 64; j++) {
            float e = __expf(row[j] * 0.125f - mxs);
            sum += e;
            ((unsigned*)row)[j] = f2tf32(e);
        }
        sum += __shfl_xor_sync(0xffffffffu, sum, 1);
        if ((tid & 1) == 0) inv_l[r] = 1.f / sum;
    }
    __syncthreads();

    // out = P @ V  (warp: 16 rows x 64 cols)
    float oacc[8][4];
#pragma unroll
    for (int nt = 0; nt < 8; nt++)
#pragma unroll
        for (int i = 0; i < 4; i++) oacc[nt][i] = 0.f;

#pragma unroll
    for (int kc = 0; kc < 16; kc++) {
        int kb = kc * 8;
        unsigned af[4];
        af[0] = Ps[(m0 + g) * PS_STR + kb + tig];
        af[1] = Ps[(m0 + 8 + g) * PS_STR + kb + tig];
        af[2] = Ps[(m0 + g) * PS_STR + kb + tig + 4];
        af[3] = Ps[(m0 + 8 + g) * PS_STR + kb + tig + 4];
#pragma unroll
        for (int nt = 0; nt < 8; nt++) {
            unsigned bf[2];
            bf[0] = Vs[(kb + tig) * V_STR + nt * 8 + g];
            bf[1] = Vs[(kb + tig + 4) * V_STR + nt * 8 + g];
            mma_tf32(oacc[nt], af, bf);
        }
    }

    float il0 = inv_l[m0 + g];
    float il1 = inv_l[m0 + 8 + g];
    // output in [S,B,A,D]: row(s) = s*256 + b*16 + a where n = a*16+b
    int a = n >> 4, b = n & 15;
    int s0 = m0 + g, s1 = m0 + 8 + g;
    size_t r0 = ((size_t)(s0 * 256 + b * 16 + a)) * 512 + h * 64;
    size_t r1 = ((size_t)(s1 * 256 + b * 16 + a)) * 512 + h * 64;
#pragma unroll
    for (int nt = 0; nt < 8; nt++) {
        int col = nt * 8 + 2 * tig;
        *(float2*)&o[r0 + col] =
            make_float2(oacc[nt][0] * il0, oacc[nt][1] * il0);
        *(float2*)&o[r1 + col] =
            make_float2(oacc[nt][2] * il1, oacc[nt][3] * il1);
    }
}

// ---------------- attention 2: per sb row (2048), seq=A=16, 8 heads ---------------
// Reads xa [S,B,A,D]; writes xf [A,B,S,D] as tf32 with K-permuted columns.
__global__ void k_attn2(const float* __restrict__ xa, unsigned* __restrict__ o) {
    __shared__ float hs[16*516];
    __shared__ float sc[16*16];
    __shared__ float ps[16*17];
    int sb = blockIdx.x;                      // s*16 + b
    int s_idx = sb >> 4, b_idx = sb & 15;
    const float4* src = (const float4*)(xa + (size_t)sb * 16 * DD);
    for (int it = threadIdx.x; it < 16*128; it += 256) {
        int r = it >> 7, c = it & 127;
        float4 vv = src[it];
        float* dst = hs + r*516 + c*4;
        dst[0]=vv.x; dst[1]=vv.y; dst[2]=vv.z; dst[3]=vv.w;
    }
    __syncthreads();
    int i = threadIdx.x >> 4;
    int j = threadIdx.x & 15;
    for (int h = 0; h < HH; h++) {
        int base = h * 64;
        const float* hi = hs + i*516 + base;
        const float* hj = hs + j*516 + base;
        float dot = 0.f;
#pragma unroll
        for (int d = 0; d < 64; d++) dot += hi[d]*hj[d];
        sc[i*16 + j] = dot * 0.125f;
        __syncthreads();
        if (threadIdx.x < 16) {
            int r = threadIdx.x;
            float m = -1e30f;
            for (int jj = 0; jj < 16; jj++) m = fmaxf(m, sc[r*16+jj]);
            float sum = 0.f;
            for (int jj = 0; jj < 16; jj++) {
                float e = __expf(sc[r*16+jj] - m);
                ps[r*17+jj] = e;
                sum += e;
            }
            float inv = 1.f / sum;
            for (int jj = 0; jj < 16; jj++) ps[r*17+jj] *= inv;
        }
        __syncthreads();
        for (int e = threadIdx.x; e < 16*64; e += 256) {
            int r = e >> 6, d = e & 63;     // r = a index
            float acc = 0.f;
#pragma unroll
            for (int jj = 0; jj < 16; jj++) acc += ps[r*17+jj] * hs[jj*516 + base + d];
            // K-permuted column within 8-group
            int dsub = d & 7;
            int dp = (d & ~7) + ((dsub < 4) ? 2*dsub : 2*(dsub - 4) + 1);
            // dst row in [A,B,S,D]: (a*16+b)*128 + s
            o[((size_t)((r*16 + b_idx)*128 + s_idx)) * DD + base + dp] = f2tf32(acc);
        }
        __syncthreads();
    }
}

// =================================================================================
extern "C" void kernel_launch(void* const* d_in, const int* in_sizes, int n_in,
                              void* d_out, int out_size) {
    const float* query = (const float*)d_in[0];
    const float* key   = (const float*)d_in[1];
    const float* value = (const float*)d_in[2];
    // d_in[3] = mask (unused by reference)
    const float* padq  = (const float*)d_in[4];
    const float* padk  = (const float*)d_in[5];
    const float* Wq    = (const float*)d_in[6];
    const float* bq    = (const float*)d_in[7];
    const float* Wk    = (const float*)d_in[8];
    const float* bk    = (const float*)d_in[9];
    const float* Wv    = (const float*)d_in[10];
    const float* bv    = (const float*)d_in[11];
    const float* Wo    = (const float*)d_in[12];
    const float* bo    = (const float*)d_in[13];
    float* out = (float*)d_out;

    unsigned *xcq, *xck, *vtf, *xf, *Wt;
    float *yq, *yk, *wq, *wk, *q, *k, *v, *xa;
    cudaGetSymbolAddress((void**)&xcq, g_xcq);
    cudaGetSymbolAddress((void**)&xck, g_xck);
    cudaGetSymbolAddress((void**)&yq,  g_yq);
    cudaGetSymbolAddress((void**)&yk,  g_yk);
    cudaGetSymbolAddress((void**)&wq,  g_wq);
    cudaGetSymbolAddress((void**)&wk,  g_wk);
    cudaGetSymbolAddress((void**)&q,   g_q);
    cudaGetSymbolAddress((void**)&k,   g_k);
    cudaGetSymbolAddress((void**)&v,   g_v);
    cudaGetSymbolAddress((void**)&vtf, g_vtf);
    cudaGetSymbolAddress((void**)&xa,  g_xa);
    cudaGetSymbolAddress((void**)&xf,  g_xf);
    cudaGetSymbolAddress((void**)&Wt,  g_Wt);

    const size_t WSZ = (size_t)DD * DD;

    // --- input conversions (K-permuted tf32) ---
    const int conc_blocks = (NN*SC*64) / 256;    // 8448
    k_concat_cvt<<<conc_blocks, 256>>>(query, padq, xcq);
    k_concat_cvt<<<conc_blocks, 256>>>(key,   padk, xck);
    k_cvt_perm<<<(int)(WSZ/8 + 255)/256, 256>>>(Wq, Wt + 0*WSZ, (int)(WSZ/8));
    k_cvt_perm<<<(int)(WSZ/8 + 255)/256, 256>>>(Wk, Wt + 1*WSZ, (int)(WSZ/8));
    k_cvt_perm<<<(int)(WSZ/8 + 255)/256, 256>>>(Wv, Wt + 2*WSZ, (int)(WSZ/8));
    k_cvt_perm<<<(int)(WSZ/8 + 255)/256, 256>>>(Wo, Wt + 3*WSZ, (int)(WSZ/8));
    k_cvt_perm<<<(NN*SS*DD/8 + 255)/256, 256>>>(value, vtf, NN*SS*DD/8);

    // --- projections (tensor-core, 2-stage cp.async, LDS.64 fragments) ---
    const int gemm_smem = 2 * 2 * P_STG * 4;     // 81920 B
    cudaFuncSetAttribute(gemm_p, cudaFuncAttributeMaxDynamicSharedMemorySize, gemm_smem);
    dim3 gproj(DD/128, (NN*SC)/128);             // (4, 264)
    gemm_p<<<gproj, 256, gemm_smem>>>(xcq, Wt + 0*WSZ, bq, yq);
    gemm_p<<<gproj, 256, gemm_smem>>>(xck, Wt + 1*WSZ, bk, yk);
    dim3 gv(DD/128, (NN*SS)/128);                // (4, 256)
    gemm_p<<<gv, 256, gemm_smem>>>(vtf, Wt + 2*WSZ, bv, v);

    // --- local window reweighting ---
    k_weights<<<(NN*SS)/4, 128>>>(yq, wq);
    k_weights<<<(NN*SS)/4, 128>>>(yk, wk);
    k_gather<<<NN*SS, 128>>>(yq, wq, q);
    k_gather<<<NN*SS, 128>>>(yk, wk, k);

    // --- attention 1 (writes [S,B,A,D]) ---
    const int attn1_smem = 26752 * 4;            // 107008 B
    cudaFuncSetAttribute(attn1_tc, cudaFuncAttributeMaxDynamicSharedMemorySize, attn1_smem);
    attn1_tc<<<NN*HH, 256, attn1_smem>>>(q, k, v, xa);

    // --- attention 2 (reads [S,B,A,D], writes K-permuted tf32 [A,B,S,D]) ---
    k_attn2<<<SS*BB, 256>>>(xa, xf);

    // --- output projection ---
    gemm_p<<<gv, 256, gemm_smem>>>(xf, Wt + 3*WSZ, bo, out);
}

// round 8
// speedup vs baseline: 1.0977x; 1.0977x over previous
#include <cuda_runtime.h>
#include <cuda_bf16.h>
#include <math.h>

// Problem constants
#define AA 16
#define BB 16
#define SS 128
#define DD 512
#define NN 256        // A*B
#define LL 5
#define SC 132        // S + L - 1
#define HH 8
#define DK 64

// ---------------- scratch (device globals; no runtime allocation) ----------------
__device__ unsigned g_xcq[(size_t)NN*SC*DD];   // tf32
__device__ unsigned g_xck[(size_t)NN*SC*DD];   // tf32
__device__ float    g_yq [(size_t)NN*SC*DD];
__device__ float    g_yk [(size_t)NN*SC*DD];
__device__ float    g_wq [(size_t)NN*SS*LL];
__device__ float    g_wk [(size_t)NN*SS*LL];
__device__ float    g_q  [(size_t)NN*SS*DD];
__device__ float    g_k  [(size_t)NN*SS*DD];
__device__ float    g_v  [(size_t)NN*SS*DD];
__device__ unsigned g_vtf[(size_t)NN*SS*DD];   // tf32 value
__device__ float    g_xa [(size_t)NN*SS*DD];   // [S,B,A,D]
__device__ unsigned g_xf [(size_t)NN*SS*DD];   // tf32 [A,B,S,D]
__device__ unsigned g_Wt [4*(size_t)DD*DD];    // tf32 Wq,Wk,Wv,Wo

// ---------------- tf32 helpers ---------------------------------------------------
__device__ __forceinline__ unsigned f2tf32(float f) {
    unsigned u;
    asm("cvt.rna.tf32.f32 %0, %1;" : "=r"(u) : "f"(f));
    return u;
}

__device__ __forceinline__ void mma_tf32(float* d, const unsigned* a, const unsigned* b) {
    asm volatile(
        "mma.sync.aligned.m16n8k8.row.col.f32.tf32.tf32.f32 "
        "{%0,%1,%2,%3}, {%4,%5,%6,%7}, {%8,%9}, {%0,%1,%2,%3};"
        : "+f"(d[0]), "+f"(d[1]), "+f"(d[2]), "+f"(d[3])
        : "r"(a[0]), "r"(a[1]), "r"(a[2]), "r"(a[3]),
          "r"(b[0]), "r"(b[1]));
}

__device__ __forceinline__ void cp16(unsigned* smem_dst, const unsigned* gmem_src) {
    unsigned saddr = (unsigned)__cvta_generic_to_shared(smem_dst);
    asm volatile("cp.async.cg.shared.global [%0], [%1], 16;\n"
                 :: "r"(saddr), "l"(gmem_src));
}

// ---------------- elementwise f32 -> tf32 ----------------------------------------
__global__ void k_cvt(const float* __restrict__ src, unsigned* __restrict__ dst, int n4) {
    int i = blockIdx.x * 256 + threadIdx.x;
    if (i < n4) {
        float4 v = ((const float4*)src)[i];
        ((uint4*)dst)[i] = make_uint4(f2tf32(v.x), f2tf32(v.y), f2tf32(v.z), f2tf32(v.w));
    }
}

// ---------------- concat pad + x -> xc [N,132,D] in tf32 --------------------------
__global__ void k_concat_cvt(const float* __restrict__ x, const float* __restrict__ pad,
                             unsigned* __restrict__ xc) {
    int idx = blockIdx.x * 256 + threadIdx.x;     // float4 index; total N*SC*128
    int c   = idx & 127;
    int row = idx >> 7;
    int n = row / SC;
    int s = row - n * SC;
    const float4* src;
    if (s < LL - 1)
        src = (const float4*)pad + ((size_t)n*(LL-1) + s)*128 + c;
    else
        src = (const float4*)x   + ((size_t)n*SS + (s - (LL-1)))*128 + c;
    float4 v = *src;
    ((uint4*)xc)[idx] = make_uint4(f2tf32(v.x), f2tf32(v.y), f2tf32(v.z), f2tf32(v.w));
}

// ---------------- tf32 tensor-core GEMM, cp.async 3-stage pipeline ---------------
#define AS_STR 36
#define STG_WORDS (128 * AS_STR)
#define NSTG 3
__global__ void __launch_bounds__(256) gemm_tc3(const unsigned* __restrict__ A,
                                                const unsigned* __restrict__ W,
                                                const float* __restrict__ bias,
                                                float* __restrict__ C) {
    extern __shared__ unsigned sm[];   // [NSTG stages][As|Bs]
    int tid = threadIdx.x;
    int bm = blockIdx.y * 128;
    int bn = blockIdx.x * 128;
    int wid = tid >> 5, lane = tid & 31;
    int g = lane >> 2, tig = lane & 3;
    int wm = wid & 3, wn = wid >> 2;
    int m0 = wm * 32, n0 = wn * 64;

    const unsigned* Ab = A + (size_t)bm * 512;
    const unsigned* Wb = W + (size_t)bn * 512;

    float acc[2][8][4];
#pragma unroll
    for (int mt = 0; mt < 2; mt++)
#pragma unroll
        for (int nt = 0; nt < 8; nt++)
#pragma unroll
            for (int i = 0; i < 4; i++) acc[mt][nt][i] = 0.f;

#define PREFETCH(kt, stg)                                                     \
    {                                                                         \
        unsigned* sA = sm + (stg) * 2 * STG_WORDS;                            \
        unsigned* sB = sA + STG_WORDS;                                        \
        _Pragma("unroll")                                                     \
        for (int i = 0; i < 4; i++) {                                         \
            int idx = tid + 256 * i;                                          \
            int r = idx >> 3, qd = idx & 7;                                   \
            cp16(sA + r * AS_STR + qd * 4, Ab + (size_t)r * 512 + (kt) + qd * 4); \
            cp16(sB + r * AS_STR + qd * 4, Wb + (size_t)r * 512 + (kt) + qd * 4); \
        }                                                                     \
        asm volatile("cp.async.commit_group;\n");                             \
    }

    PREFETCH(0, 0);
    PREFETCH(32, 1);

#pragma unroll 1
    for (int kt = 0; kt < 512; kt += 32) {
        int it = kt >> 5;
        int stg = it % NSTG;
        asm volatile("cp.async.wait_group 1;\n");
        __syncthreads();
        if (kt + 64 < 512) {
            PREFETCH(kt + 64, (stg + 2) % NSTG);
        } else {
            asm volatile("cp.async.commit_group;\n");
        }

        const unsigned* As = sm + stg * 2 * STG_WORDS;
        const unsigned* Bs = As + STG_WORDS;
#pragma unroll
        for (int kc = 0; kc < 4; kc++) {
            int kb = kc * 8;
            unsigned af[2][4], bf[8][2];
#pragma unroll
            for (int mt = 0; mt < 2; mt++) {
                int row = m0 + mt * 16 + g;
                af[mt][0] = As[row * AS_STR + kb + tig];
                af[mt][1] = As[(row + 8) * AS_STR + kb + tig];
                af[mt][2] = As[row * AS_STR + kb + tig + 4];
                af[mt][3] = As[(row + 8) * AS_STR + kb + tig + 4];
            }
#pragma unroll
            for (int nt = 0; nt < 8; nt++) {
                int col = n0 + nt * 8 + g;
                bf[nt][0] = Bs[col * AS_STR + kb + tig];
                bf[nt][1] = Bs[col * AS_STR + kb + tig + 4];
            }
#pragma unroll
            for (int mt = 0; mt < 2; mt++)
#pragma unroll
                for (int nt = 0; nt < 8; nt++)
                    mma_tf32(acc[mt][nt], af[mt], bf[nt]);
        }
    }
#undef PREFETCH

#pragma unroll
    for (int mt = 0; mt < 2; mt++) {
        int row = bm + m0 + mt * 16 + g;
#pragma unroll
        for (int nt = 0; nt < 8; nt++) {
            int col = bn + n0 + nt * 8 + 2 * tig;
            float b0 = bias[col], b1 = bias[col + 1];
            float2 lo = make_float2(acc[mt][nt][0] + b0, acc[mt][nt][1] + b1);
            float2 hi = make_float2(acc[mt][nt][2] + b0, acc[mt][nt][3] + b1);
            *(float2*)&C[(size_t)row * 512 + col] = lo;
            *(float2*)&C[(size_t)(row + 8) * 512 + col] = hi;
        }
    }
}

// ---------------- local-window softmax weights: w[n,s,5] --------------------------
__global__ void k_weights(const float* __restrict__ y, float* __restrict__ w) {
    int gw = blockIdx.x * 4 + (threadIdx.x >> 5);   // warp -> (n,s)
    int lane = threadIdx.x & 31;
    int n = gw >> 7;
    int s = gw & 127;
    const float* base = y + (size_t)n * SC * DD;
    const float* cen  = base + (size_t)(s + LL - 1) * DD;
    float d0=0.f,d1=0.f,d2=0.f,d3=0.f,d4=0.f;
    for (int i = lane; i < DD; i += 32) {
        float cv = cen[i];
        d0 += cv * base[(s+0)*DD + i];
        d1 += cv * base[(s+1)*DD + i];
        d2 += cv * base[(s+2)*DD + i];
        d3 += cv * base[(s+3)*DD + i];
        d4 += cv * base[(s+4)*DD + i];
    }
#pragma unroll
    for (int off = 16; off; off >>= 1) {
        d0 += __shfl_xor_sync(0xffffffffu, d0, off);
        d1 += __shfl_xor_sync(0xffffffffu, d1, off);
        d2 += __shfl_xor_sync(0xffffffffu, d2, off);
        d3 += __shfl_xor_sync(0xffffffffu, d3, off);
        d4 += __shfl_xor_sync(0xffffffffu, d4, off);
    }
    if (lane == 0) {
        const float sc = 0.044194173824159216f;  // 1/sqrt(512)
        float s0 = d0*sc, s1 = d1*sc, s2 = d2*sc, s3 = d3*sc, s4 = d4*sc;
        float m = fmaxf(fmaxf(fmaxf(s0,s1), fmaxf(s2,s3)), s4);
        float e0 = __expf(s0-m), e1 = __expf(s1-m), e2 = __expf(s2-m),
              e3 = __expf(s3-m), e4 = __expf(s4-m);
        float inv = 1.f / (e0+e1+e2+e3+e4);
        float* wp = w + (size_t)gw * LL;
        wp[0]=e0*inv; wp[1]=e1*inv; wp[2]=e2*inv; wp[3]=e3*inv; wp[4]=e4*inv;
    }
}

// ---------------- scrambled-reshape gather ---------------------------------------
__global__ void k_gather(const float* __restrict__ y, const float* __restrict__ w,
                         float* __restrict__ out) {
    int ns = blockIdx.x;           // n*128 + s
    int n = ns >> 7;
    int s = ns & 127;
    float coef[LL];
    int   rowi[LL];
#pragma unroll
    for (int l = 0; l < LL; l++) {
        int f  = l * SS + s;
        int sp = f / 5;
        int lp = f - sp * 5;
        coef[l] = w[((size_t)n * SS + sp) * LL + lp];
        rowi[l] = sp + lp;
    }
    const float4* yb = (const float4*)y + (size_t)n * SC * 128;
    int c = threadIdx.x;   // 0..127 float4 lanes
    float4 acc = make_float4(0.f,0.f,0.f,0.f);
#pragma unroll
    for (int l = 0; l < LL; l++) {
        float4 v = yb[(size_t)rowi[l] * 128 + c];
        acc.x += coef[l]*v.x; acc.y += coef[l]*v.y;
        acc.z += coef[l]*v.z; acc.w += coef[l]*v.w;
    }
    ((float4*)out)[(size_t)ns * 128 + c] = acc;
}

// ---------------- attention 1 via tf32 MMA: per (n,h) block, S=128, dk=64 --------
#define Q_STR 68
#define V_STR 72
#define PS_STR 132
__global__ void __launch_bounds__(256) attn1_tc(const float* __restrict__ q,
                                                const float* __restrict__ k,
                                                const float* __restrict__ v,
                                                float* __restrict__ o) {
    extern __shared__ unsigned sm[];
    unsigned* Qs = sm;
    unsigned* Ks = sm + 128 * Q_STR;
    unsigned* Ps = sm;                       // overlay (valid after QK phase)
    unsigned* Vs = sm + 2 * 128 * Q_STR;
    float* inv_l = (float*)(Vs + 128 * V_STR);

    int n = blockIdx.x >> 3, h = blockIdx.x & 7;
    int tid = threadIdx.x;
    int lane = tid & 31;
    int g = lane >> 2, tig = lane & 3;
    int m0 = (tid >> 5) * 16;                // warp -> 16 rows

#pragma unroll
    for (int i = 0; i < 8; i++) {
        int idx = tid + 256 * i;             // 0..2047
        int s = idx >> 4, dq = idx & 15;
        size_t goff = ((size_t)(n * 128 + s)) * 512 + h * 64 + dq * 4;
        float4 vq = *(const float4*)(q + goff);
        float4 vk = *(const float4*)(k + goff);
        float4 vv = *(const float4*)(v + goff);
        *(uint4*)&Qs[s * Q_STR + dq * 4] =
            make_uint4(f2tf32(vq.x), f2tf32(vq.y), f2tf32(vq.z), f2tf32(vq.w));
        *(uint4*)&Ks[s * Q_STR + dq * 4] =
            make_uint4(f2tf32(vk.x), f2tf32(vk.y), f2tf32(vk.z), f2tf32(vk.w));
        *(uint4*)&Vs[s * V_STR + dq * 4] =
            make_uint4(f2tf32(vv.x), f2tf32(vv.y), f2tf32(vv.z), f2tf32(vv.w));
    }
    __syncthreads();

    float acc[16][4];
#pragma unroll
    for (int nt = 0; nt < 16; nt++)
#pragma unroll
        for (int i = 0; i < 4; i++) acc[nt][i] = 0.f;

#pragma unroll
    for (int kc = 0; kc < 8; kc++) {
        int kb = kc * 8;
        unsigned af[4];
        af[0] = Qs[(m0 + g) * Q_STR + kb + tig];
        af[1] = Qs[(m0 + 8 + g) * Q_STR + kb + tig];
        af[2] = Qs[(m0 + g) * Q_STR + kb + tig + 4];
        af[3] = Qs[(m0 + 8 + g) * Q_STR + kb + tig + 4];
#pragma unroll
        for (int nt = 0; nt < 16; nt++) {
            unsigned bf[2];
            bf[0] = Ks[(nt * 8 + g) * Q_STR + kb + tig];
            bf[1] = Ks[(nt * 8 + g) * Q_STR + kb + tig + 4];
            mma_tf32(acc[nt], af, bf);
        }
    }
    __syncthreads();   // Q,K dead everywhere -> safe to overlay Ps

    float* Pf = (float*)Ps;
#pragma unroll
    for (int nt = 0; nt < 16; nt++) {
        int col = nt * 8 + 2 * tig;
        Pf[(m0 + g) * PS_STR + col]     = acc[nt][0];
        Pf[(m0 + g) * PS_STR + col + 1] = acc[nt][1];
        Pf[(m0 + 8 + g) * PS_STR + col]     = acc[nt][2];
        Pf[(m0 + 8 + g) * PS_STR + col + 1] = acc[nt][3];
    }
    __syncthreads();

    {
        int r = tid >> 1;
        int halfc = (tid & 1) * 64;
        float* row = Pf + r * PS_STR + halfc;
        float mx = -1e30f;
#pragma unroll
        for (int j = 0; j < 64; j++) mx = fmaxf(mx, row[j]);
        mx = fmaxf(mx, __shfl_xor_sync(0xffffffffu, mx, 1));
        float mxs = mx * 0.125f;
        float sum = 0.f;
#pragma unroll
        for (int j = 0; j < 64; j++) {
            float e = __expf(row[j] * 0.125f - mxs);
            sum += e;
            ((unsigned*)row)[j] = f2tf32(e);
        }
        sum += __shfl_xor_sync(0xffffffffu, sum, 1);
        if ((tid & 1) == 0) inv_l[r] = 1.f / sum;
    }
    __syncthreads();

    float oacc[8][4];
#pragma unroll
    for (int nt = 0; nt < 8; nt++)
#pragma unroll
        for (int i = 0; i < 4; i++) oacc[nt][i] = 0.f;

#pragma unroll
    for (int kc = 0; kc < 16; kc++) {
        int kb = kc * 8;
        unsigned af[4];
        af[0] = Ps[(m0 + g) * PS_STR + kb + tig];
        af[1] = Ps[(m0 + 8 + g) * PS_STR + kb + tig];
        af[2] = Ps[(m0 + g) * PS_STR + kb + tig + 4];
        af[3] = Ps[(m0 + 8 + g) * PS_STR + kb + tig + 4];
#pragma unroll
        for (int nt = 0; nt < 8; nt++) {
            unsigned bf[2];
            bf[0] = Vs[(kb + tig) * V_STR + nt * 8 + g];
            bf[1] = Vs[(kb + tig + 4) * V_STR + nt * 8 + g];
            mma_tf32(oacc[nt], af, bf);
        }
    }

    float il0 = inv_l[m0 + g];
    float il1 = inv_l[m0 + 8 + g];
    int a = n >> 4, b = n & 15;
    int s0 = m0 + g, s1 = m0 + 8 + g;
    size_t r0 = ((size_t)(s0 * 256 + b * 16 + a)) * 512 + h * 64;
    size_t r1 = ((size_t)(s1 * 256 + b * 16 + a)) * 512 + h * 64;
#pragma unroll
    for (int nt = 0; nt < 8; nt++) {
        int col = nt * 8 + 2 * tig;
        *(float2*)&o[r0 + col] =
            make_float2(oacc[nt][0] * il0, oacc[nt][1] * il0);
        *(float2*)&o[r1 + col] =
            make_float2(oacc[nt][2] * il1, oacc[nt][3] * il1);
    }
}

// ---------------- attention 2 via tf32 MMA: block per sb, 4 warps x 2 heads ------
// Reads xa [S,B,A,D]; writes xf [A,B,S,D] as tf32 (fuses transpose+cvt).
// H_STR = 516 (full 512-col row + pad 4; 516 % 32 = 4 -> conflict-free frags)
#define H_STR 516
#define PW_STR 20
__global__ void __launch_bounds__(128) attn2_tc(const float* __restrict__ xa,
                                                unsigned* __restrict__ o) {
    __shared__ unsigned hsu[16 * H_STR];
    __shared__ unsigned Pw[4][16 * PW_STR];
    int sb = blockIdx.x;                      // s*16 + b
    int s_idx = sb >> 4, b_idx = sb & 15;
    int tid = threadIdx.x;
    int wid = tid >> 5, lane = tid & 31;
    int g = lane >> 2, tig = lane & 3;

    // load 16x512 tile, convert to tf32
    const float4* src = (const float4*)(xa + (size_t)sb * 16 * DD);
#pragma unroll
    for (int i = 0; i < 16; i++) {
        int it = tid + 128 * i;               // 0..2047
        int r = it >> 7, c = it & 127;
        float4 v = src[it];
        *(uint4*)&hsu[r * H_STR + c * 4] =
            make_uint4(f2tf32(v.x), f2tf32(v.y), f2tf32(v.z), f2tf32(v.w));
    }
    __syncthreads();

    unsigned* ps = &Pw[wid][0];
#pragma unroll
    for (int hh = 0; hh < 2; hh++) {
        int base = (wid * 2 + hh) * 64;

        // QK^T: 16x16, K=64
        float c[2][4];
#pragma unroll
        for (int nt = 0; nt < 2; nt++)
#pragma unroll
            for (int i = 0; i < 4; i++) c[nt][i] = 0.f;
#pragma unroll
        for (int kc = 0; kc < 8; kc++) {
            int kb = kc * 8;
            unsigned af[4];
            af[0] = hsu[g * H_STR + base + kb + tig];
            af[1] = hsu[(g + 8) * H_STR + base + kb + tig];
            af[2] = hsu[g * H_STR + base + kb + tig + 4];
            af[3] = hsu[(g + 8) * H_STR + base + kb + tig + 4];
#pragma unroll
            for (int nt = 0; nt < 2; nt++) {
                unsigned bf[2];
                bf[0] = hsu[(nt * 8 + g) * H_STR + base + kb + tig];
                bf[1] = hsu[(nt * 8 + g) * H_STR + base + kb + tig + 4];
                mma_tf32(c[nt], af, bf);
            }
        }

        // softmax over 16 cols; rows g (c[*][0..1]) and g+8 (c[*][2..3])
        float m0 = fmaxf(fmaxf(c[0][0], c[0][1]), fmaxf(c[1][0], c[1][1]));
        float m1 = fmaxf(fmaxf(c[0][2], c[0][3]), fmaxf(c[1][2], c[1][3]));
        m0 = fmaxf(m0, __shfl_xor_sync(0xffffffffu, m0, 1));
        m0 = fmaxf(m0, __shfl_xor_sync(0xffffffffu, m0, 2));
        m1 = fmaxf(m1, __shfl_xor_sync(0xffffffffu, m1, 1));
        m1 = fmaxf(m1, __shfl_xor_sync(0xffffffffu, m1, 2));
        float m0s = m0 * 0.125f, m1s = m1 * 0.125f;
        float e[2][4];
#pragma unroll
        for (int nt = 0; nt < 2; nt++) {
            e[nt][0] = __expf(c[nt][0] * 0.125f - m0s);
            e[nt][1] = __expf(c[nt][1] * 0.125f - m0s);
            e[nt][2] = __expf(c[nt][2] * 0.125f - m1s);
            e[nt][3] = __expf(c[nt][3] * 0.125f - m1s);
        }
        float s0 = e[0][0] + e[0][1] + e[1][0] + e[1][1];
        float s1 = e[0][2] + e[0][3] + e[1][2] + e[1][3];
        s0 += __shfl_xor_sync(0xffffffffu, s0, 1);
        s0 += __shfl_xor_sync(0xffffffffu, s0, 2);
        s1 += __shfl_xor_sync(0xffffffffu, s1, 1);
        s1 += __shfl_xor_sync(0xffffffffu, s1, 2);
        float inv0 = 1.f / s0, inv1 = 1.f / s1;

        // stage unnormalized P (tf32) in per-warp smem
#pragma unroll
        for (int nt = 0; nt < 2; nt++) {
            int col = nt * 8 + 2 * tig;
            *(uint2*)&ps[g * PW_STR + col] =
                make_uint2(f2tf32(e[nt][0]), f2tf32(e[nt][1]));
            *(uint2*)&ps[(g + 8) * PW_STR + col] =
                make_uint2(f2tf32(e[nt][2]), f2tf32(e[nt][3]));
        }
        __syncwarp();

        // out = P(16x16) @ V(16x64)
        float oc[8][4];
#pragma unroll
        for (int nt = 0; nt < 8; nt++)
#pragma unroll
            for (int i = 0; i < 4; i++) oc[nt][i] = 0.f;
#pragma unroll
        for (int kc = 0; kc < 2; kc++) {
            int kb = kc * 8;
            unsigned af[4];
            af[0] = ps[g * PW_STR + kb + tig];
            af[1] = ps[(g + 8) * PW_STR + kb + tig];
            af[2] = ps[g * PW_STR + kb + tig + 4];
            af[3] = ps[(g + 8) * PW_STR + kb + tig + 4];
#pragma unroll
            for (int nt = 0; nt < 8; nt++) {
                unsigned bf[2];
                bf[0] = hsu[(kb + tig) * H_STR + base + nt * 8 + g];
                bf[1] = hsu[(kb + tig + 4) * H_STR + base + nt * 8 + g];
                mma_tf32(oc[nt], af, bf);
            }
        }

        // write out: a = row index; dst row in [A,B,S,D] = (a*16+b)*128 + s
        size_t r0 = ((size_t)((g * 16 + b_idx) * 128 + s_idx)) * 512 + base;
        size_t r1 = ((size_t)(((g + 8) * 16 + b_idx) * 128 + s_idx)) * 512 + base;
#pragma unroll
        for (int nt = 0; nt < 8; nt++) {
            int col = nt * 8 + 2 * tig;
            *(uint2*)&o[r0 + col] =
                make_uint2(f2tf32(oc[nt][0] * inv0), f2tf32(oc[nt][1] * inv0));
            *(uint2*)&o[r1 + col] =
                make_uint2(f2tf32(oc[nt][2] * inv1), f2tf32(oc[nt][3] * inv1));
        }
        __syncwarp();
    }
}

// =================================================================================
extern "C" void kernel_launch(void* const* d_in, const int* in_sizes, int n_in,
                              void* d_out, int out_size) {
    const float* query = (const float*)d_in[0];
    const float* key   = (const float*)d_in[1];
    const float* value = (const float*)d_in[2];
    // d_in[3] = mask (unused by reference)
    const float* padq  = (const float*)d_in[4];
    const float* padk  = (const float*)d_in[5];
    const float* Wq    = (const float*)d_in[6];
    const float* bq    = (const float*)d_in[7];
    const float* Wk    = (const float*)d_in[8];
    const float* bk    = (const float*)d_in[9];
    const float* Wv    = (const float*)d_in[10];
    const float* bv    = (const float*)d_in[11];
    const float* Wo    = (const float*)d_in[12];
    const float* bo    = (const float*)d_in[13];
    float* out = (float*)d_out;

    unsigned *xcq, *xck, *vtf, *xf, *Wt;
    float *yq, *yk, *wq, *wk, *q, *k, *v, *xa;
    cudaGetSymbolAddress((void**)&xcq, g_xcq);
    cudaGetSymbolAddress((void**)&xck, g_xck);
    cudaGetSymbolAddress((void**)&yq,  g_yq);
    cudaGetSymbolAddress((void**)&yk,  g_yk);
    cudaGetSymbolAddress((void**)&wq,  g_wq);
    cudaGetSymbolAddress((void**)&wk,  g_wk);
    cudaGetSymbolAddress((void**)&q,   g_q);
    cudaGetSymbolAddress((void**)&k,   g_k);
    cudaGetSymbolAddress((void**)&v,   g_v);
    cudaGetSymbolAddress((void**)&vtf, g_vtf);
    cudaGetSymbolAddress((void**)&xa,  g_xa);
    cudaGetSymbolAddress((void**)&xf,  g_xf);
    cudaGetSymbolAddress((void**)&Wt,  g_Wt);

    const size_t WSZ = (size_t)DD * DD;

    // --- input conversions ---
    const int conc_blocks = (NN*SC*128) / 256;   // 16896
    k_concat_cvt<<<conc_blocks, 256>>>(query, padq, xcq);
    k_concat_cvt<<<conc_blocks, 256>>>(key,   padk, xck);
    k_cvt<<<(int)(WSZ/4 + 255)/256, 256>>>(Wq, Wt + 0*WSZ, (int)(WSZ/4));
    k_cvt<<<(int)(WSZ/4 + 255)/256, 256>>>(Wk, Wt + 1*WSZ, (int)(WSZ/4));
    k_cvt<<<(int)(WSZ/4 + 255)/256, 256>>>(Wv, Wt + 2*WSZ, (int)(WSZ/4));
    k_cvt<<<(int)(WSZ/4 + 255)/256, 256>>>(Wo, Wt + 3*WSZ, (int)(WSZ/4));
    k_cvt<<<(NN*SS*DD/4 + 255)/256, 256>>>(value, vtf, NN*SS*DD/4);

    // --- projections (tensor-core, cp.async 3-stage pipelined) ---
    const int gemm_smem = NSTG * 2 * STG_WORDS * 4;   // 110592 B
    cudaFuncSetAttribute(gemm_tc3, cudaFuncAttributeMaxDynamicSharedMemorySize, gemm_smem);
    dim3 gproj(DD/128, (NN*SC)/128);             // (4, 264)
    gemm_tc3<<<gproj, 256, gemm_smem>>>(xcq, Wt + 0*WSZ, bq, yq);
    gemm_tc3<<<gproj, 256, gemm_smem>>>(xck, Wt + 1*WSZ, bk, yk);
    dim3 gv(DD/128, (NN*SS)/128);                // (4, 256)
    gemm_tc3<<<gv, 256, gemm_smem>>>(vtf, Wt + 2*WSZ, bv, v);

    // --- local window reweighting ---
    k_weights<<<(NN*SS)/4, 128>>>(yq, wq);
    k_weights<<<(NN*SS)/4, 128>>>(yk, wk);
    k_gather<<<NN*SS, 128>>>(yq, wq, q);
    k_gather<<<NN*SS, 128>>>(yk, wk, k);

    // --- attention 1 (writes [S,B,A,D]) ---
    const int attn1_smem = 26752 * 4;            // 107008 B
    cudaFuncSetAttribute(attn1_tc, cudaFuncAttributeMaxDynamicSharedMemorySize, attn1_smem);
    attn1_tc<<<NN*HH, 256, attn1_smem>>>(q, k, v, xa);

    // --- attention 2 (tensor-core; reads [S,B,A,D], writes tf32 [A,B,S,D]) ---
    attn2_tc<<<SS*BB, 128>>>(xa, xf);

    // --- output projection ---
    gemm_tc3<<<gv, 256, gemm_smem>>>(xf, Wt + 3*WSZ, bo, out);
}

// round 9
// speedup vs baseline: 1.6278x; 1.4829x over previous
#include <cuda_runtime.h>
#include <cuda_fp16.h>
#include <cuda_bf16.h>
#include <math.h>

// Problem constants
#define AA 16
#define BB 16
#define SS 128
#define DD 512
#define NN 256        // A*B
#define LL 5
#define SC 132        // S + L - 1
#define HH 8
#define DK 64

// ---------------- scratch (device globals; no runtime allocation) ----------------
__device__ __half g_xcq[(size_t)NN*SC*DD];     // fp16
__device__ __half g_xck[(size_t)NN*SC*DD];     // fp16
__device__ float  g_yq [(size_t)NN*SC*DD];
__device__ float  g_yk [(size_t)NN*SC*DD];
__device__ float  g_wq [(size_t)NN*SS*LL];
__device__ float  g_wk [(size_t)NN*SS*LL];
__device__ float  g_q  [(size_t)NN*SS*DD];
__device__ float  g_k  [(size_t)NN*SS*DD];
__device__ float  g_v  [(size_t)NN*SS*DD];
__device__ __half g_vh [(size_t)NN*SS*DD];     // fp16 value
__device__ float  g_xa [(size_t)NN*SS*DD];     // [S,B,A,D]
__device__ __half g_xf [(size_t)NN*SS*DD];     // fp16 [A,B,S,D]
__device__ __half g_Wh [4*(size_t)DD*DD];      // fp16 Wq,Wk,Wv,Wo

// ---------------- helpers ---------------------------------------------------------
__device__ __forceinline__ unsigned f2tf32(float f) {
    unsigned u;
    asm("cvt.rna.tf32.f32 %0, %1;" : "=r"(u) : "f"(f));
    return u;
}

__device__ __forceinline__ void mma_tf32(float* d, const unsigned* a, const unsigned* b) {
    asm volatile(
        "mma.sync.aligned.m16n8k8.row.col.f32.tf32.tf32.f32 "
        "{%0,%1,%2,%3}, {%4,%5,%6,%7}, {%8,%9}, {%0,%1,%2,%3};"
        : "+f"(d[0]), "+f"(d[1]), "+f"(d[2]), "+f"(d[3])
        : "r"(a[0]), "r"(a[1]), "r"(a[2]), "r"(a[3]),
          "r"(b[0]), "r"(b[1]));
}

// fp16 m16n8k16, fp32 accumulate
__device__ __forceinline__ void mma_f16(float* d, const unsigned* a, const unsigned* b) {
    asm volatile(
        "mma.sync.aligned.m16n8k16.row.col.f32.f16.f16.f32 "
        "{%0,%1,%2,%3}, {%4,%5,%6,%7}, {%8,%9}, {%0,%1,%2,%3};"
        : "+f"(d[0]), "+f"(d[1]), "+f"(d[2]), "+f"(d[3])
        : "r"(a[0]), "r"(a[1]), "r"(a[2]), "r"(a[3]),
          "r"(b[0]), "r"(b[1]));
}

__device__ __forceinline__ void cp16(unsigned* smem_dst, const void* gmem_src) {
    unsigned saddr = (unsigned)__cvta_generic_to_shared(smem_dst);
    asm volatile("cp.async.cg.shared.global [%0], [%1], 16;\n"
                 :: "r"(saddr), "l"(gmem_src));
}

__device__ __forceinline__ unsigned pack_h2(float a, float b) {
    __half2 h = __floats2half2_rn(a, b);
    return *(unsigned*)&h;
}

// ---------------- elementwise f32 -> fp16 -----------------------------------------
__global__ void k_cvt_h(const float* __restrict__ src, __half* __restrict__ dst, int n4) {
    int i = blockIdx.x * 256 + threadIdx.x;
    if (i < n4) {
        float4 v = ((const float4*)src)[i];
        uint2 u = make_uint2(pack_h2(v.x, v.y), pack_h2(v.z, v.w));
        ((uint2*)dst)[i] = u;
    }
}

// ---------------- concat pad + x -> xc [N,132,D] in fp16 --------------------------
__global__ void k_concat_cvt(const float* __restrict__ x, const float* __restrict__ pad,
                             __half* __restrict__ xc) {
    int idx = blockIdx.x * 256 + threadIdx.x;     // float4 index; total N*SC*128
    int c   = idx & 127;
    int row = idx >> 7;
    int n = row / SC;
    int s = row - n * SC;
    const float4* src;
    if (s < LL - 1)
        src = (const float4*)pad + ((size_t)n*(LL-1) + s)*128 + c;
    else
        src = (const float4*)x   + ((size_t)n*SS + (s - (LL-1)))*128 + c;
    float4 v = *src;
    ((uint2*)xc)[idx] = make_uint2(pack_h2(v.x, v.y), pack_h2(v.z, v.w));
}

// ---------------- fp16 tensor-core GEMM: C[M,512] = A[M,512]@W[512,512]^T + bias --
// 128x128 block tile, BK=64 halfs, 2-stage cp.async, 256 threads (8 warps 4m x 2n),
// warp tile 32x64. Smem rows: 64 halfs + 8 pad = 72 halfs = 36 words.
#define GS 36
#define GSTG (128 * GS)
__global__ void __launch_bounds__(256) gemm_h(const __half* __restrict__ A,
                                              const __half* __restrict__ W,
                                              const float* __restrict__ bias,
                                              float* __restrict__ C) {
    extern __shared__ unsigned sm[];   // [2 stages][As|Bs]
    int tid = threadIdx.x;
    int bm = blockIdx.y * 128;
    int bn = blockIdx.x * 128;
    int wid = tid >> 5, lane = tid & 31;
    int g = lane >> 2, tig = lane & 3;
    int wm = wid & 3, wn = wid >> 2;
    int m0 = wm * 32, n0 = wn * 64;

    const __half* Ab = A + (size_t)bm * 512;
    const __half* Wb = W + (size_t)bn * 512;

    float acc[2][8][4];
#pragma unroll
    for (int mt = 0; mt < 2; mt++)
#pragma unroll
        for (int nt = 0; nt < 8; nt++)
#pragma unroll
            for (int i = 0; i < 4; i++) acc[mt][nt][i] = 0.f;

#define PREFETCH(kt, stg)                                                        \
    {                                                                            \
        unsigned* sA = sm + (stg) * 2 * GSTG;                                    \
        unsigned* sB = sA + GSTG;                                                \
        _Pragma("unroll")                                                        \
        for (int i = 0; i < 4; i++) {                                            \
            int idx = tid + 256 * i;                                             \
            int r = idx >> 3, qd = idx & 7;                                      \
            cp16(sA + r * GS + qd * 4, Ab + (size_t)r * 512 + (kt) + qd * 8);    \
            cp16(sB + r * GS + qd * 4, Wb + (size_t)r * 512 + (kt) + qd * 8);    \
        }                                                                        \
        asm volatile("cp.async.commit_group;\n");                                \
    }

    PREFETCH(0, 0);

#pragma unroll 1
    for (int kt = 0; kt < 512; kt += 64) {
        int stg = (kt >> 6) & 1;
        if (kt + 64 < 512) {
            PREFETCH(kt + 64, stg ^ 1);
            asm volatile("cp.async.wait_group 1;\n");
        } else {
            asm volatile("cp.async.wait_group 0;\n");
        }
        __syncthreads();

        const unsigned* As = sm + stg * 2 * GSTG;
        const unsigned* Bs = As + GSTG;
#pragma unroll
        for (int kc = 0; kc < 4; kc++) {
            int kb2 = kc * 8;                 // word offset within row
            unsigned af[2][4], bf[8][2];
#pragma unroll
            for (int mt = 0; mt < 2; mt++) {
                int row = m0 + mt * 16 + g;
                af[mt][0] = As[row * GS + kb2 + tig];
                af[mt][1] = As[(row + 8) * GS + kb2 + tig];
                af[mt][2] = As[row * GS + kb2 + tig + 4];
                af[mt][3] = As[(row + 8) * GS + kb2 + tig + 4];
            }
#pragma unroll
            for (int nt = 0; nt < 8; nt++) {
                int col = n0 + nt * 8 + g;
                bf[nt][0] = Bs[col * GS + kb2 + tig];
                bf[nt][1] = Bs[col * GS + kb2 + tig + 4];
            }
#pragma unroll
            for (int mt = 0; mt < 2; mt++)
#pragma unroll
                for (int nt = 0; nt < 8; nt++)
                    mma_f16(acc[mt][nt], af[mt], bf[nt]);
        }
        __syncthreads();
    }
#undef PREFETCH

#pragma unroll
    for (int mt = 0; mt < 2; mt++) {
        int row = bm + m0 + mt * 16 + g;
#pragma unroll
        for (int nt = 0; nt < 8; nt++) {
            int col = bn + n0 + nt * 8 + 2 * tig;
            float b0 = bias[col], b1 = bias[col + 1];
            float2 lo = make_float2(acc[mt][nt][0] + b0, acc[mt][nt][1] + b1);
            float2 hi = make_float2(acc[mt][nt][2] + b0, acc[mt][nt][3] + b1);
            *(float2*)&C[(size_t)row * 512 + col] = lo;
            *(float2*)&C[(size_t)(row + 8) * 512 + col] = hi;
        }
    }
}

// ---------------- local-window softmax weights: w[n,s,5] --------------------------
__global__ void k_weights(const float* __restrict__ y, float* __restrict__ w) {
    int gw = blockIdx.x * 4 + (threadIdx.x >> 5);   // warp -> (n,s)
    int lane = threadIdx.x & 31;
    int n = gw >> 7;
    int s = gw & 127;
    const float* base = y + (size_t)n * SC * DD;
    const float* cen  = base + (size_t)(s + LL - 1) * DD;
    float d0=0.f,d1=0.f,d2=0.f,d3=0.f,d4=0.f;
    for (int i = lane; i < DD; i += 32) {
        float cv = cen[i];
        d0 += cv * base[(s+0)*DD + i];
        d1 += cv * base[(s+1)*DD + i];
        d2 += cv * base[(s+2)*DD + i];
        d3 += cv * base[(s+3)*DD + i];
        d4 += cv * base[(s+4)*DD + i];
    }
#pragma unroll
    for (int off = 16; off; off >>= 1) {
        d0 += __shfl_xor_sync(0xffffffffu, d0, off);
        d1 += __shfl_xor_sync(0xffffffffu, d1, off);
        d2 += __shfl_xor_sync(0xffffffffu, d2, off);
        d3 += __shfl_xor_sync(0xffffffffu, d3, off);
        d4 += __shfl_xor_sync(0xffffffffu, d4, off);
    }
    if (lane == 0) {
        const float sc = 0.044194173824159216f;  // 1/sqrt(512)
        float s0 = d0*sc, s1 = d1*sc, s2 = d2*sc, s3 = d3*sc, s4 = d4*sc;
        float m = fmaxf(fmaxf(fmaxf(s0,s1), fmaxf(s2,s3)), s4);
        float e0 = __expf(s0-m), e1 = __expf(s1-m), e2 = __expf(s2-m),
              e3 = __expf(s3-m), e4 = __expf(s4-m);
        float inv = 1.f / (e0+e1+e2+e3+e4);
        float* wp = w + (size_t)gw * LL;
        wp[0]=e0*inv; wp[1]=e1*inv; wp[2]=e2*inv; wp[3]=e3*inv; wp[4]=e4*inv;
    }
}

// ---------------- scrambled-reshape gather ---------------------------------------
__global__ void k_gather(const float* __restrict__ y, const float* __restrict__ w,
                         float* __restrict__ out) {
    int ns = blockIdx.x;           // n*128 + s
    int n = ns >> 7;
    int s = ns & 127;
    float coef[LL];
    int   rowi[LL];
#pragma unroll
    for (int l = 0; l < LL; l++) {
        int f  = l * SS + s;
        int sp = f / 5;
        int lp = f - sp * 5;
        coef[l] = w[((size_t)n * SS + sp) * LL + lp];
        rowi[l] = sp + lp;
    }
    const float4* yb = (const float4*)y + (size_t)n * SC * 128;
    int c = threadIdx.x;   // 0..127 float4 lanes
    float4 acc = make_float4(0.f,0.f,0.f,0.f);
#pragma unroll
    for (int l = 0; l < LL; l++) {
        float4 v = yb[(size_t)rowi[l] * 128 + c];
        acc.x += coef[l]*v.x; acc.y += coef[l]*v.y;
        acc.z += coef[l]*v.z; acc.w += coef[l]*v.w;
    }
    ((float4*)out)[(size_t)ns * 128 + c] = acc;
}

// ---------------- attention 1 via fp16 MMA: per (n,h) block, S=128, dk=64 --------
// Register softmax (quad shuffles), V staged transposed, writes [S,B,A,D] fp32.
// halfs layout: Qh @0 (128x72), Kh @9216 (128x72), Ps overlays @0 (128x136),
//               Vt @18432 (64x136). Total 27136 halfs = 54272 B.
#define A1_QS 36    // word stride Q/K rows (72 halfs)
#define A1_PS 68    // word stride P rows (136 halfs)
#define A1_VS 68    // word stride Vt rows (136 halfs)
__global__ void __launch_bounds__(256) attn1_h(const float* __restrict__ q,
                                               const float* __restrict__ k,
                                               const float* __restrict__ v,
                                               float* __restrict__ o) {
    extern __shared__ __half hs[];
    __half* Qh = hs;
    __half* Kh = hs + 9216;
    __half* Ph = hs;                   // overlay after QK phase
    __half* Vt = hs + 18432;
    unsigned* Qw = (unsigned*)Qh;
    unsigned* Kw = (unsigned*)Kh;
    unsigned* Pw = (unsigned*)Ph;
    unsigned* Vw = (unsigned*)Vt;

    int n = blockIdx.x >> 3, h = blockIdx.x & 7;
    int tid = threadIdx.x;
    int lane = tid & 31;
    int g = lane >> 2, tig = lane & 3;
    int m0 = (tid >> 5) * 16;          // warp -> 16 rows

    // stage Q,K (row-major halfs) and V transposed [d][s]
#pragma unroll
    for (int i = 0; i < 8; i++) {
        int idx = tid + 256 * i;       // 0..2047 = 128 s x 16 dq
        int s = idx >> 4, dq = idx & 15;
        size_t goff = ((size_t)(n * 128 + s)) * 512 + h * 64 + dq * 4;
        float4 vq = *(const float4*)(q + goff);
        float4 vk = *(const float4*)(k + goff);
        float4 vv = *(const float4*)(v + goff);
        *(uint2*)&Qh[s * 72 + dq * 4] = make_uint2(pack_h2(vq.x, vq.y), pack_h2(vq.z, vq.w));
        *(uint2*)&Kh[s * 72 + dq * 4] = make_uint2(pack_h2(vk.x, vk.y), pack_h2(vk.z, vk.w));
        int d0 = dq * 4;
        Vt[(d0+0) * 136 + s] = __float2half(vv.x);
        Vt[(d0+1) * 136 + s] = __float2half(vv.y);
        Vt[(d0+2) * 136 + s] = __float2half(vv.z);
        Vt[(d0+3) * 136 + s] = __float2half(vv.w);
    }
    __syncthreads();

    // scores = Q @ K^T (warp: rows m0+g, m0+8+g across all 128 cols)
    float acc[16][4];
#pragma unroll
    for (int nt = 0; nt < 16; nt++)
#pragma unroll
        for (int i = 0; i < 4; i++) acc[nt][i] = 0.f;

#pragma unroll
    for (int kc = 0; kc < 4; kc++) {   // K=64 -> 4 x k16
        int kb2 = kc * 8;
        unsigned af[4];
        af[0] = Qw[(m0 + g) * A1_QS + kb2 + tig];
        af[1] = Qw[(m0 + 8 + g) * A1_QS + kb2 + tig];
        af[2] = Qw[(m0 + g) * A1_QS + kb2 + tig + 4];
        af[3] = Qw[(m0 + 8 + g) * A1_QS + kb2 + tig + 4];
#pragma unroll
        for (int nt = 0; nt < 16; nt++) {
            unsigned bf[2];
            bf[0] = Kw[(nt * 8 + g) * A1_QS + kb2 + tig];
            bf[1] = Kw[(nt * 8 + g) * A1_QS + kb2 + tig + 4];
            mma_f16(acc[nt], af, bf);
        }
    }
    __syncthreads();   // Q/K dead in all warps -> safe to overlay P

    // register softmax over 128 cols (cols split across the 4 quad lanes)
    float mx0 = -1e30f, mx1 = -1e30f;
#pragma unroll
    for (int nt = 0; nt < 16; nt++) {
        mx0 = fmaxf(mx0, fmaxf(acc[nt][0], acc[nt][1]));
        mx1 = fmaxf(mx1, fmaxf(acc[nt][2], acc[nt][3]));
    }
    mx0 = fmaxf(mx0, __shfl_xor_sync(0xffffffffu, mx0, 1));
    mx0 = fmaxf(mx0, __shfl_xor_sync(0xffffffffu, mx0, 2));
    mx1 = fmaxf(mx1, __shfl_xor_sync(0xffffffffu, mx1, 1));
    mx1 = fmaxf(mx1, __shfl_xor_sync(0xffffffffu, mx1, 2));
    float sum0 = 0.f, sum1 = 0.f;
#pragma unroll
    for (int nt = 0; nt < 16; nt++) {
        float e0 = __expf(0.125f * (acc[nt][0] - mx0));
        float e1 = __expf(0.125f * (acc[nt][1] - mx0));
        float e2 = __expf(0.125f * (acc[nt][2] - mx1));
        float e3 = __expf(0.125f * (acc[nt][3] - mx1));
        sum0 += e0 + e1;
        sum1 += e2 + e3;
        int cw = nt * 4 + tig;         // word col = (nt*8 + 2tig)/2
        Pw[(m0 + g) * A1_PS + cw]     = pack_h2(e0, e1);
        Pw[(m0 + 8 + g) * A1_PS + cw] = pack_h2(e2, e3);
    }
    sum0 += __shfl_xor_sync(0xffffffffu, sum0, 1);
    sum0 += __shfl_xor_sync(0xffffffffu, sum0, 2);
    sum1 += __shfl_xor_sync(0xffffffffu, sum1, 1);
    sum1 += __shfl_xor_sync(0xffffffffu, sum1, 2);
    float inv0 = 1.f / sum0, inv1 = 1.f / sum1;
    __syncwarp();   // own-warp P rows complete (A-frags read own rows only)

    // out = P @ V  (K = 128 -> 8 x k16; B from Vt[d][s])
    float oacc[8][4];
#pragma unroll
    for (int nt = 0; nt < 8; nt++)
#pragma unroll
        for (int i = 0; i < 4; i++) oacc[nt][i] = 0.f;

#pragma unroll
    for (int kc = 0; kc < 8; kc++) {
        int kb2 = kc * 8;
        unsigned af[4];
        af[0] = Pw[(m0 + g) * A1_PS + kb2 + tig];
        af[1] = Pw[(m0 + 8 + g) * A1_PS + kb2 + tig];
        af[2] = Pw[(m0 + g) * A1_PS + kb2 + tig + 4];
        af[3] = Pw[(m0 + 8 + g) * A1_PS + kb2 + tig + 4];
#pragma unroll
        for (int nt = 0; nt < 8; nt++) {
            unsigned bf[2];
            bf[0] = Vw[(nt * 8 + g) * A1_VS + kb2 + tig];
            bf[1] = Vw[(nt * 8 + g) * A1_VS + kb2 + tig + 4];
            mma_f16(oacc[nt], af, bf);
        }
    }

    // output in [S,B,A,D]: row(s) = s*256 + b*16 + a where n = a*16+b
    int a = n >> 4, b = n & 15;
    int s0 = m0 + g, s1 = m0 + 8 + g;
    size_t r0 = ((size_t)(s0 * 256 + b * 16 + a)) * 512 + h * 64;
    size_t r1 = ((size_t)(s1 * 256 + b * 16 + a)) * 512 + h * 64;
#pragma unroll
    for (int nt = 0; nt < 8; nt++) {
        int col = nt * 8 + 2 * tig;
        *(float2*)&o[r0 + col] =
            make_float2(oacc[nt][0] * inv0, oacc[nt][1] * inv0);
        *(float2*)&o[r1 + col] =
            make_float2(oacc[nt][2] * inv1, oacc[nt][3] * inv1);
    }
}

// ---------------- attention 2 via tf32 MMA: block per sb, 4 warps x 2 heads ------
// Reads xa [S,B,A,D] fp32; writes xf [A,B,S,D] as fp16 (fuses transpose+cvt).
#define H_STR 516
#define PW_STR 20
__global__ void __launch_bounds__(128) attn2_tc(const float* __restrict__ xa,
                                                __half* __restrict__ o) {
    __shared__ unsigned hsu[16 * H_STR];
    __shared__ unsigned Pw2[4][16 * PW_STR];
    int sb = blockIdx.x;                      // s*16 + b
    int s_idx = sb >> 4, b_idx = sb & 15;
    int tid = threadIdx.x;
    int wid = tid >> 5, lane = tid & 31;
    int g = lane >> 2, tig = lane & 3;

    const float4* src = (const float4*)(xa + (size_t)sb * 16 * DD);
#pragma unroll
    for (int i = 0; i < 16; i++) {
        int it = tid + 128 * i;               // 0..2047
        int r = it >> 7, c = it & 127;
        float4 v = src[it];
        *(uint4*)&hsu[r * H_STR + c * 4] =
            make_uint4(f2tf32(v.x), f2tf32(v.y), f2tf32(v.z), f2tf32(v.w));
    }
    __syncthreads();

    unsigned* ps = &Pw2[wid][0];
#pragma unroll
    for (int hh = 0; hh < 2; hh++) {
        int base = (wid * 2 + hh) * 64;

        float c[2][4];
#pragma unroll
        for (int nt = 0; nt < 2; nt++)
#pragma unroll
            for (int i = 0; i < 4; i++) c[nt][i] = 0.f;
#pragma unroll
        for (int kc = 0; kc < 8; kc++) {
            int kb = kc * 8;
            unsigned af[4];
            af[0] = hsu[g * H_STR + base + kb + tig];
            af[1] = hsu[(g + 8) * H_STR + base + kb + tig];
            af[2] = hsu[g * H_STR + base + kb + tig + 4];
            af[3] = hsu[(g + 8) * H_STR + base + kb + tig + 4];
#pragma unroll
            for (int nt = 0; nt < 2; nt++) {
                unsigned bf[2];
                bf[0] = hsu[(nt * 8 + g) * H_STR + base + kb + tig];
                bf[1] = hsu[(nt * 8 + g) * H_STR + base + kb + tig + 4];
                mma_tf32(c[nt], af, bf);
            }
        }

        float m0 = fmaxf(fmaxf(c[0][0], c[0][1]), fmaxf(c[1][0], c[1][1]));
        float m1 = fmaxf(fmaxf(c[0][2], c[0][3]), fmaxf(c[1][2], c[1][3]));
        m0 = fmaxf(m0, __shfl_xor_sync(0xffffffffu, m0, 1));
        m0 = fmaxf(m0, __shfl_xor_sync(0xffffffffu, m0, 2));
        m1 = fmaxf(m1, __shfl_xor_sync(0xffffffffu, m1, 1));
        m1 = fmaxf(m1, __shfl_xor_sync(0xffffffffu, m1, 2));
        float m0s = m0 * 0.125f, m1s = m1 * 0.125f;
        float e[2][4];
#pragma unroll
        for (int nt = 0; nt < 2; nt++) {
            e[nt][0] = __expf(c[nt][0] * 0.125f - m0s);
            e[nt][1] = __expf(c[nt][1] * 0.125f - m0s);
            e[nt][2] = __expf(c[nt][2] * 0.125f - m1s);
            e[nt][3] = __expf(c[nt][3] * 0.125f - m1s);
        }
        float s0 = e[0][0] + e[0][1] + e[1][0] + e[1][1];
        float s1 = e[0][2] + e[0][3] + e[1][2] + e[1][3];
        s0 += __shfl_xor_sync(0xffffffffu, s0, 1);
        s0 += __shfl_xor_sync(0xffffffffu, s0, 2);
        s1 += __shfl_xor_sync(0xffffffffu, s1, 1);
        s1 += __shfl_xor_sync(0xffffffffu, s1, 2);
        float inv0 = 1.f / s0, inv1 = 1.f / s1;

#pragma unroll
        for (int nt = 0; nt < 2; nt++) {
            int col = nt * 8 + 2 * tig;
            *(uint2*)&ps[g * PW_STR + col] =
                make_uint2(f2tf32(e[nt][0]), f2tf32(e[nt][1]));
            *(uint2*)&ps[(g + 8) * PW_STR + col] =
                make_uint2(f2tf32(e[nt][2]), f2tf32(e[nt][3]));
        }
        __syncwarp();

        float oc[8][4];
#pragma unroll
        for (int nt = 0; nt < 8; nt++)
#pragma unroll
            for (int i = 0; i < 4; i++) oc[nt][i] = 0.f;
#pragma unroll
        for (int kc = 0; kc < 2; kc++) {
            int kb = kc * 8;
            unsigned af[4];
            af[0] = ps[g * PW_STR + kb + tig];
            af[1] = ps[(g + 8) * PW_STR + kb + tig];
            af[2] = ps[g * PW_STR + kb + tig + 4];
            af[3] = ps[(g + 8) * PW_STR + kb + tig + 4];
#pragma unroll
            for (int nt = 0; nt < 8; nt++) {
                unsigned bf[2];
                bf[0] = hsu[(kb + tig) * H_STR + base + nt * 8 + g];
                bf[1] = hsu[(kb + tig + 4) * H_STR + base + nt * 8 + g];
                mma_tf32(oc[nt], af, bf);
            }
        }

        // dst row in [A,B,S,D]: (a*16+b)*128 + s ; fp16 output
        size_t r0 = ((size_t)((g * 16 + b_idx) * 128 + s_idx)) * 512 + base;
        size_t r1 = ((size_t)(((g + 8) * 16 + b_idx) * 128 + s_idx)) * 512 + base;
#pragma unroll
        for (int nt = 0; nt < 8; nt++) {
            int col = nt * 8 + 2 * tig;
            *(unsigned*)&o[r0 + col] = pack_h2(oc[nt][0] * inv0, oc[nt][1] * inv0);
            *(unsigned*)&o[r1 + col] = pack_h2(oc[nt][2] * inv1, oc[nt][3] * inv1);
        }
        __syncwarp();
    }
}

// =================================================================================
extern "C" void kernel_launch(void* const* d_in, const int* in_sizes, int n_in,
                              void* d_out, int out_size) {
    const float* query = (const float*)d_in[0];
    const float* key   = (const float*)d_in[1];
    const float* value = (const float*)d_in[2];
    // d_in[3] = mask (unused by reference)
    const float* padq  = (const float*)d_in[4];
    const float* padk  = (const float*)d_in[5];
    const float* Wq    = (const float*)d_in[6];
    const float* bq    = (const float*)d_in[7];
    const float* Wk    = (const float*)d_in[8];
    const float* bk    = (const float*)d_in[9];
    const float* Wv    = (const float*)d_in[10];
    const float* bv    = (const float*)d_in[11];
    const float* Wo    = (const float*)d_in[12];
    const float* bo    = (const float*)d_in[13];
    float* out = (float*)d_out;

    __half *xcq, *xck, *vh, *xf, *Wh;
    float *yq, *yk, *wq, *wk, *q, *k, *v, *xa;
    cudaGetSymbolAddress((void**)&xcq, g_xcq);
    cudaGetSymbolAddress((void**)&xck, g_xck);
    cudaGetSymbolAddress((void**)&yq,  g_yq);
    cudaGetSymbolAddress((void**)&yk,  g_yk);
    cudaGetSymbolAddress((void**)&wq,  g_wq);
    cudaGetSymbolAddress((void**)&wk,  g_wk);
    cudaGetSymbolAddress((void**)&q,   g_q);
    cudaGetSymbolAddress((void**)&k,   g_k);
    cudaGetSymbolAddress((void**)&v,   g_v);
    cudaGetSymbolAddress((void**)&vh,  g_vh);
    cudaGetSymbolAddress((void**)&xa,  g_xa);
    cudaGetSymbolAddress((void**)&xf,  g_xf);
    cudaGetSymbolAddress((void**)&Wh,  g_Wh);

    const size_t WSZ = (size_t)DD * DD;

    // --- input conversions (fp16) ---
    const int conc_blocks = (NN*SC*128) / 256;   // 16896
    k_concat_cvt<<<conc_blocks, 256>>>(query, padq, xcq);
    k_concat_cvt<<<conc_blocks, 256>>>(key,   padk, xck);
    k_cvt_h<<<(int)(WSZ/4 + 255)/256, 256>>>(Wq, Wh + 0*WSZ, (int)(WSZ/4));
    k_cvt_h<<<(int)(WSZ/4 + 255)/256, 256>>>(Wk, Wh + 1*WSZ, (int)(WSZ/4));
    k_cvt_h<<<(int)(WSZ/4 + 255)/256, 256>>>(Wv, Wh + 2*WSZ, (int)(WSZ/4));
    k_cvt_h<<<(int)(WSZ/4 + 255)/256, 256>>>(Wo, Wh + 3*WSZ, (int)(WSZ/4));
    k_cvt_h<<<(NN*SS*DD/4 + 255)/256, 256>>>(value, vh, NN*SS*DD/4);

    // --- projections (fp16 tensor-core, 2-stage cp.async) ---
    const int gemm_smem = 2 * 2 * GSTG * 4;      // 73728 B
    cudaFuncSetAttribute(gemm_h, cudaFuncAttributeMaxDynamicSharedMemorySize, gemm_smem);
    dim3 gproj(DD/128, (NN*SC)/128);             // (4, 264)
    gemm_h<<<gproj, 256, gemm_smem>>>(xcq, Wh + 0*WSZ, bq, yq);
    gemm_h<<<gproj, 256, gemm_smem>>>(xck, Wh + 1*WSZ, bk, yk);
    dim3 gv(DD/128, (NN*SS)/128);                // (4, 256)
    gemm_h<<<gv, 256, gemm_smem>>>(vh, Wh + 2*WSZ, bv, v);

    // --- local window reweighting ---
    k_weights<<<(NN*SS)/4, 128>>>(yq, wq);
    k_weights<<<(NN*SS)/4, 128>>>(yk, wk);
    k_gather<<<NN*SS, 128>>>(yq, wq, q);
    k_gather<<<NN*SS, 128>>>(yk, wk, k);

    // --- attention 1 (fp16 MMA, register softmax; writes [S,B,A,D]) ---
    const int attn1_smem = 27136 * 2;            // 54272 B
    cudaFuncSetAttribute(attn1_h, cudaFuncAttributeMaxDynamicSharedMemorySize, attn1_smem);
    attn1_h<<<NN*HH, 256, attn1_smem>>>(q, k, v, xa);

    // --- attention 2 (tf32 core; reads [S,B,A,D], writes fp16 [A,B,S,D]) ---
    attn2_tc<<<SS*BB, 128>>>(xa, xf);

    // --- output projection ---
    gemm_h<<<gv, 256, gemm_smem>>>(xf, Wh + 3*WSZ, bo, out);
}

// round 10
// speedup vs baseline: 1.8002x; 1.1059x over previous
#include <cuda_runtime.h>
#include <cuda_fp16.h>
#include <cuda_bf16.h>
#include <math.h>

// Problem constants
#define AA 16
#define BB 16
#define SS 128
#define DD 512
#define NN 256        // A*B
#define LL 5
#define SC 132        // S + L - 1
#define HH 8
#define DK 64

// ---------------- scratch (device globals; no runtime allocation) ----------------
__device__ __half g_xcq[(size_t)NN*SC*DD];     // fp16 concat(q)
__device__ __half g_xck[(size_t)NN*SC*DD];     // fp16 concat(k)
__device__ __half g_yqh[(size_t)NN*SC*DD];     // fp16 projected q
__device__ __half g_ykh[(size_t)NN*SC*DD];     // fp16 projected k
__device__ float  g_wq [(size_t)NN*SS*LL];
__device__ float  g_wk [(size_t)NN*SS*LL];
__device__ __half g_qh [(size_t)NN*SS*DD];     // fp16 gathered q
__device__ __half g_kh [(size_t)NN*SS*DD];     // fp16 gathered k
__device__ __half g_vh [(size_t)NN*SS*DD];     // fp16 value (input cvt)
__device__ __half g_vh2[(size_t)NN*SS*DD];     // fp16 projected v
__device__ __half g_xah[(size_t)NN*SS*DD];     // fp16 [S,B,A,D]
__device__ __half g_xf [(size_t)NN*SS*DD];     // fp16 [A,B,S,D]
__device__ __half g_Wh [4*(size_t)DD*DD];      // fp16 Wq,Wk,Wv,Wo

// ---------------- helpers ---------------------------------------------------------
__device__ __forceinline__ unsigned f2tf32(float f) {
    unsigned u;
    asm("cvt.rna.tf32.f32 %0, %1;" : "=r"(u) : "f"(f));
    return u;
}

__device__ __forceinline__ void mma_tf32(float* d, const unsigned* a, const unsigned* b) {
    asm volatile(
        "mma.sync.aligned.m16n8k8.row.col.f32.tf32.tf32.f32 "
        "{%0,%1,%2,%3}, {%4,%5,%6,%7}, {%8,%9}, {%0,%1,%2,%3};"
        : "+f"(d[0]), "+f"(d[1]), "+f"(d[2]), "+f"(d[3])
        : "r"(a[0]), "r"(a[1]), "r"(a[2]), "r"(a[3]),
          "r"(b[0]), "r"(b[1]));
}

// fp16 m16n8k16, fp32 accumulate
__device__ __forceinline__ void mma_f16(float* d, const unsigned* a, const unsigned* b) {
    asm volatile(
        "mma.sync.aligned.m16n8k16.row.col.f32.f16.f16.f32 "
        "{%0,%1,%2,%3}, {%4,%5,%6,%7}, {%8,%9}, {%0,%1,%2,%3};"
        : "+f"(d[0]), "+f"(d[1]), "+f"(d[2]), "+f"(d[3])
        : "r"(a[0]), "r"(a[1]), "r"(a[2]), "r"(a[3]),
          "r"(b[0]), "r"(b[1]));
}

__device__ __forceinline__ void cp16(unsigned* smem_dst, const void* gmem_src) {
    unsigned saddr = (unsigned)__cvta_generic_to_shared(smem_dst);
    asm volatile("cp.async.cg.shared.global [%0], [%1], 16;\n"
                 :: "r"(saddr), "l"(gmem_src));
}

__device__ __forceinline__ unsigned pack_h2(float a, float b) {
    __half2 h = __floats2half2_rn(a, b);
    return *(unsigned*)&h;
}

// epilogue store: 2 consecutive cols
__device__ __forceinline__ void store2(float* C, size_t idx, float a, float b) {
    *(float2*)&C[idx] = make_float2(a, b);
}
__device__ __forceinline__ void store2(__half* C, size_t idx, float a, float b) {
    *(unsigned*)&C[idx] = pack_h2(a, b);
}

// ---------------- elementwise f32 -> fp16 -----------------------------------------
__global__ void k_cvt_h(const float* __restrict__ src, __half* __restrict__ dst, int n4) {
    int i = blockIdx.x * 256 + threadIdx.x;
    if (i < n4) {
        float4 v = ((const float4*)src)[i];
        ((uint2*)dst)[i] = make_uint2(pack_h2(v.x, v.y), pack_h2(v.z, v.w));
    }
}

// ---------------- concat pad + x -> xc [N,132,D] in fp16 --------------------------
__global__ void k_concat_cvt(const float* __restrict__ x, const float* __restrict__ pad,
                             __half* __restrict__ xc) {
    int idx = blockIdx.x * 256 + threadIdx.x;     // float4 index; total N*SC*128
    int c   = idx & 127;
    int row = idx >> 7;
    int n = row / SC;
    int s = row - n * SC;
    const float4* src;
    if (s < LL - 1)
        src = (const float4*)pad + ((size_t)n*(LL-1) + s)*128 + c;
    else
        src = (const float4*)x   + ((size_t)n*SS + (s - (LL-1)))*128 + c;
    float4 v = *src;
    ((uint2*)xc)[idx] = make_uint2(pack_h2(v.x, v.y), pack_h2(v.z, v.w));
}

// ---------------- fp16 tensor-core GEMM: C[M,512] = A[M,512]@W[512,512]^T + bias --
// 128x128 block tile, BK=64 halfs, 2-stage cp.async, 256 threads (8 warps 4m x 2n),
// warp tile 32x64. Smem rows: 64 halfs + 8 pad = 72 halfs = 36 words.
#define GS 36
#define GSTG (128 * GS)
template<class T>
__global__ void __launch_bounds__(256) gemm_h(const __half* __restrict__ A,
                                              const __half* __restrict__ W,
                                              const float* __restrict__ bias,
                                              T* __restrict__ C) {
    extern __shared__ unsigned sm[];   // [2 stages][As|Bs]
    int tid = threadIdx.x;
    int bm = blockIdx.y * 128;
    int bn = blockIdx.x * 128;
    int wid = tid >> 5, lane = tid & 31;
    int g = lane >> 2, tig = lane & 3;
    int wm = wid & 3, wn = wid >> 2;
    int m0 = wm * 32, n0 = wn * 64;

    const __half* Ab = A + (size_t)bm * 512;
    const __half* Wb = W + (size_t)bn * 512;

    float acc[2][8][4];
#pragma unroll
    for (int mt = 0; mt < 2; mt++)
#pragma unroll
        for (int nt = 0; nt < 8; nt++)
#pragma unroll
            for (int i = 0; i < 4; i++) acc[mt][nt][i] = 0.f;

#define PREFETCH(kt, stg)                                                        \
    {                                                                            \
        unsigned* sA = sm + (stg) * 2 * GSTG;                                    \
        unsigned* sB = sA + GSTG;                                                \
        _Pragma("unroll")                                                        \
        for (int i = 0; i < 4; i++) {                                            \
            int idx = tid + 256 * i;                                             \
            int r = idx >> 3, qd = idx & 7;                                      \
            cp16(sA + r * GS + qd * 4, Ab + (size_t)r * 512 + (kt) + qd * 8);    \
            cp16(sB + r * GS + qd * 4, Wb + (size_t)r * 512 + (kt) + qd * 8);    \
        }                                                                        \
        asm volatile("cp.async.commit_group;\n");                                \
    }

    PREFETCH(0, 0);

#pragma unroll 1
    for (int kt = 0; kt < 512; kt += 64) {
        int stg = (kt >> 6) & 1;
        if (kt + 64 < 512) {
            PREFETCH(kt + 64, stg ^ 1);
            asm volatile("cp.async.wait_group 1;\n");
        } else {
            asm volatile("cp.async.wait_group 0;\n");
        }
        __syncthreads();

        const unsigned* As = sm + stg * 2 * GSTG;
        const unsigned* Bs = As + GSTG;
#pragma unroll
        for (int kc = 0; kc < 4; kc++) {
            int kb2 = kc * 8;                 // word offset within row
            unsigned af[2][4], bf[8][2];
#pragma unroll
            for (int mt = 0; mt < 2; mt++) {
                int row = m0 + mt * 16 + g;
                af[mt][0] = As[row * GS + kb2 + tig];
                af[mt][1] = As[(row + 8) * GS + kb2 + tig];
                af[mt][2] = As[row * GS + kb2 + tig + 4];
                af[mt][3] = As[(row + 8) * GS + kb2 + tig + 4];
            }
#pragma unroll
            for (int nt = 0; nt < 8; nt++) {
                int col = n0 + nt * 8 + g;
                bf[nt][0] = Bs[col * GS + kb2 + tig];
                bf[nt][1] = Bs[col * GS + kb2 + tig + 4];
            }
#pragma unroll
            for (int mt = 0; mt < 2; mt++)
#pragma unroll
                for (int nt = 0; nt < 8; nt++)
                    mma_f16(acc[mt][nt], af[mt], bf[nt]);
        }
        __syncthreads();
    }
#undef PREFETCH

#pragma unroll
    for (int mt = 0; mt < 2; mt++) {
        int row = bm + m0 + mt * 16 + g;
#pragma unroll
        for (int nt = 0; nt < 8; nt++) {
            int col = bn + n0 + nt * 8 + 2 * tig;
            float b0 = bias[col], b1 = bias[col + 1];
            store2(C, (size_t)row * 512 + col, acc[mt][nt][0] + b0, acc[mt][nt][1] + b1);
            store2(C, (size_t)(row + 8) * 512 + col, acc[mt][nt][2] + b0, acc[mt][nt][3] + b1);
        }
    }
}

// ---------------- local-window softmax weights from fp16 y: w[n,s,5] --------------
__global__ void k_weights(const __half* __restrict__ y, float* __restrict__ w) {
    int gw = blockIdx.x * 4 + (threadIdx.x >> 5);   // warp -> (n,s)
    int lane = threadIdx.x & 31;
    int n = gw >> 7;
    int s = gw & 127;
    const __half2* base = (const __half2*)(y + (size_t)n * SC * DD);
    const __half2* cen  = base + (size_t)(s + LL - 1) * 256;
    float d0=0.f,d1=0.f,d2=0.f,d3=0.f,d4=0.f;
    for (int i = lane; i < 256; i += 32) {
        float2 cv = __half22float2(cen[i]);
        float2 v0 = __half22float2(base[(s+0)*256 + i]);
        float2 v1 = __half22float2(base[(s+1)*256 + i]);
        float2 v2 = __half22float2(base[(s+2)*256 + i]);
        float2 v3 = __half22float2(base[(s+3)*256 + i]);
        float2 v4 = __half22float2(base[(s+4)*256 + i]);
        d0 += cv.x*v0.x + cv.y*v0.y;
        d1 += cv.x*v1.x + cv.y*v1.y;
        d2 += cv.x*v2.x + cv.y*v2.y;
        d3 += cv.x*v3.x + cv.y*v3.y;
        d4 += cv.x*v4.x + cv.y*v4.y;
    }
#pragma unroll
    for (int off = 16; off; off >>= 1) {
        d0 += __shfl_xor_sync(0xffffffffu, d0, off);
        d1 += __shfl_xor_sync(0xffffffffu, d1, off);
        d2 += __shfl_xor_sync(0xffffffffu, d2, off);
        d3 += __shfl_xor_sync(0xffffffffu, d3, off);
        d4 += __shfl_xor_sync(0xffffffffu, d4, off);
    }
    if (lane == 0) {
        const float sc = 0.044194173824159216f;  // 1/sqrt(512)
        float s0 = d0*sc, s1 = d1*sc, s2 = d2*sc, s3 = d3*sc, s4 = d4*sc;
        float m = fmaxf(fmaxf(fmaxf(s0,s1), fmaxf(s2,s3)), s4);
        float e0 = __expf(s0-m), e1 = __expf(s1-m), e2 = __expf(s2-m),
              e3 = __expf(s3-m), e4 = __expf(s4-m);
        float inv = 1.f / (e0+e1+e2+e3+e4);
        float* wp = w + (size_t)gw * LL;
        wp[0]=e0*inv; wp[1]=e1*inv; wp[2]=e2*inv; wp[3]=e3*inv; wp[4]=e4*inv;
    }
}

// ---------------- scrambled-reshape gather (fp16 in/out) --------------------------
__global__ void k_gather(const __half* __restrict__ y, const float* __restrict__ w,
                         __half* __restrict__ out) {
    int ns = blockIdx.x;           // n*128 + s
    int n = ns >> 7;
    int s = ns & 127;
    float coef[LL];
    int   rowi[LL];
#pragma unroll
    for (int l = 0; l < LL; l++) {
        int f  = l * SS + s;
        int sp = f / 5;
        int lp = f - sp * 5;
        coef[l] = w[((size_t)n * SS + sp) * LL + lp];
        rowi[l] = sp + lp;
    }
    const uint2* yb = (const uint2*)y + (size_t)n * SC * 128;  // 128 uint2 per row
    int c = threadIdx.x;   // 0..127 (4 halfs each)
    float4 acc = make_float4(0.f,0.f,0.f,0.f);
#pragma unroll
    for (int l = 0; l < LL; l++) {
        uint2 u = yb[(size_t)rowi[l] * 128 + c];
        float2 f0 = __half22float2(*(__half2*)&u.x);
        float2 f1 = __half22float2(*(__half2*)&u.y);
        acc.x += coef[l]*f0.x; acc.y += coef[l]*f0.y;
        acc.z += coef[l]*f1.x; acc.w += coef[l]*f1.y;
    }
    ((uint2*)out)[(size_t)ns * 128 + c] =
        make_uint2(pack_h2(acc.x, acc.y), pack_h2(acc.z, acc.w));
}

// ---------------- attention 1 via fp16 MMA: per (n,h) block, S=128, dk=64 --------
// fp16 q/k/v inputs, fp16 [S,B,A,D] output. Register softmax.
// halfs layout: Qh @0 (128x72), Kh @9216 (128x72), P overlays @0 (128x136),
//               Vt @18432 (64x136). Total 27136 halfs = 54272 B.
#define A1_QS 36    // word stride Q/K rows (72 halfs)
#define A1_PS 68    // word stride P rows (136 halfs)
#define A1_VS 68    // word stride Vt rows (136 halfs)
__global__ void __launch_bounds__(256) attn1_h(const __half* __restrict__ q,
                                               const __half* __restrict__ k,
                                               const __half* __restrict__ v,
                                               __half* __restrict__ o) {
    extern __shared__ __half hs[];
    __half* Qh = hs;
    __half* Kh = hs + 9216;
    __half* Vt = hs + 18432;
    unsigned* Qw = (unsigned*)Qh;
    unsigned* Kw = (unsigned*)Kh;
    unsigned* Pw = (unsigned*)hs;      // overlay after QK phase
    unsigned* Vw = (unsigned*)Vt;

    int n = blockIdx.x >> 3, h = blockIdx.x & 7;
    int tid = threadIdx.x;
    int lane = tid & 31;
    int g = lane >> 2, tig = lane & 3;
    int m0 = (tid >> 5) * 16;          // warp -> 16 rows

    // stage Q,K: raw fp16 copies (8 halfs/thread/iter)
#pragma unroll
    for (int i = 0; i < 4; i++) {
        int idx = tid + 256 * i;       // 0..1023 = 128 s x 8 dq
        int s = idx >> 3, dq = idx & 7;
        size_t goff = ((size_t)(n * 128 + s)) * 512 + h * 64 + dq * 8;
        *(uint4*)&Qh[s * 72 + dq * 8] = *(const uint4*)(q + goff);
        *(uint4*)&Kh[s * 72 + dq * 8] = *(const uint4*)(k + goff);
    }
    // stage V transposed [d][s] (4 halfs/thread/iter)
#pragma unroll
    for (int i = 0; i < 8; i++) {
        int idx = tid + 256 * i;       // 0..2047 = 128 s x 16 dq
        int s = idx >> 4, dq = idx & 15;
        size_t goff = ((size_t)(n * 128 + s)) * 512 + h * 64 + dq * 4;
        uint2 u = *(const uint2*)(v + goff);
        __half t[4];
        *(uint2*)t = u;
        int d0 = dq * 4;
        Vt[(d0+0) * 136 + s] = t[0];
        Vt[(d0+1) * 136 + s] = t[1];
        Vt[(d0+2) * 136 + s] = t[2];
        Vt[(d0+3) * 136 + s] = t[3];
    }
    __syncthreads();

    // scores = Q @ K^T (warp: rows m0+g, m0+8+g across all 128 cols)
    float acc[16][4];
#pragma unroll
    for (int nt = 0; nt < 16; nt++)
#pragma unroll
        for (int i = 0; i < 4; i++) acc[nt][i] = 0.f;

#pragma unroll
    for (int kc = 0; kc < 4; kc++) {   // K=64 -> 4 x k16
        int kb2 = kc * 8;
        unsigned af[4];
        af[0] = Qw[(m0 + g) * A1_QS + kb2 + tig];
        af[1] = Qw[(m0 + 8 + g) * A1_QS + kb2 + tig];
        af[2] = Qw[(m0 + g) * A1_QS + kb2 + tig + 4];
        af[3] = Qw[(m0 + 8 + g) * A1_QS + kb2 + tig + 4];
#pragma unroll
        for (int nt = 0; nt < 16; nt++) {
            unsigned bf[2];
            bf[0] = Kw[(nt * 8 + g) * A1_QS + kb2 + tig];
            bf[1] = Kw[(nt * 8 + g) * A1_QS + kb2 + tig + 4];
            mma_f16(acc[nt], af, bf);
        }
    }
    __syncthreads();   // Q/K dead in all warps -> safe to overlay P

    // register softmax over 128 cols (cols split across the 4 quad lanes)
    float mx0 = -1e30f, mx1 = -1e30f;
#pragma unroll
    for (int nt = 0; nt < 16; nt++) {
        mx0 = fmaxf(mx0, fmaxf(acc[nt][0], acc[nt][1]));
        mx1 = fmaxf(mx1, fmaxf(acc[nt][2], acc[nt][3]));
    }
    mx0 = fmaxf(mx0, __shfl_xor_sync(0xffffffffu, mx0, 1));
    mx0 = fmaxf(mx0, __shfl_xor_sync(0xffffffffu, mx0, 2));
    mx1 = fmaxf(mx1, __shfl_xor_sync(0xffffffffu, mx1, 1));
    mx1 = fmaxf(mx1, __shfl_xor_sync(0xffffffffu, mx1, 2));
    float sum0 = 0.f, sum1 = 0.f;
#pragma unroll
    for (int nt = 0; nt < 16; nt++) {
        float e0 = __expf(0.125f * (acc[nt][0] - mx0));
        float e1 = __expf(0.125f * (acc[nt][1] - mx0));
        float e2 = __expf(0.125f * (acc[nt][2] - mx1));
        float e3 = __expf(0.125f * (acc[nt][3] - mx1));
        sum0 += e0 + e1;
        sum1 += e2 + e3;
        int cw = nt * 4 + tig;         // word col = (nt*8 + 2tig)/2
        Pw[(m0 + g) * A1_PS + cw]     = pack_h2(e0, e1);
        Pw[(m0 + 8 + g) * A1_PS + cw] = pack_h2(e2, e3);
    }
    sum0 += __shfl_xor_sync(0xffffffffu, sum0, 1);
    sum0 += __shfl_xor_sync(0xffffffffu, sum0, 2);
    sum1 += __shfl_xor_sync(0xffffffffu, sum1, 1);
    sum1 += __shfl_xor_sync(0xffffffffu, sum1, 2);
    float inv0 = 1.f / sum0, inv1 = 1.f / sum1;
    __syncwarp();   // own-warp P rows complete (A-frags read own rows only)

    // out = P @ V  (K = 128 -> 8 x k16; B from Vt[d][s])
    float oacc[8][4];
#pragma unroll
    for (int nt = 0; nt < 8; nt++)
#pragma unroll
        for (int i = 0; i < 4; i++) oacc[nt][i] = 0.f;

#pragma unroll
    for (int kc = 0; kc < 8; kc++) {
        int kb2 = kc * 8;
        unsigned af[4];
        af[0] = Pw[(m0 + g) * A1_PS + kb2 + tig];
        af[1] = Pw[(m0 + 8 + g) * A1_PS + kb2 + tig];
        af[2] = Pw[(m0 + g) * A1_PS + kb2 + tig + 4];
        af[3] = Pw[(m0 + 8 + g) * A1_PS + kb2 + tig + 4];
#pragma unroll
        for (int nt = 0; nt < 8; nt++) {
            unsigned bf[2];
            bf[0] = Vw[(nt * 8 + g) * A1_VS + kb2 + tig];
            bf[1] = Vw[(nt * 8 + g) * A1_VS + kb2 + tig + 4];
            mma_f16(oacc[nt], af, bf);
        }
    }

    // output in [S,B,A,D] fp16: row(s) = s*256 + b*16 + a where n = a*16+b
    int a = n >> 4, b = n & 15;
    int s0 = m0 + g, s1 = m0 + 8 + g;
    size_t r0 = ((size_t)(s0 * 256 + b * 16 + a)) * 512 + h * 64;
    size_t r1 = ((size_t)(s1 * 256 + b * 16 + a)) * 512 + h * 64;
#pragma unroll
    for (int nt = 0; nt < 8; nt++) {
        int col = nt * 8 + 2 * tig;
        *(unsigned*)&o[r0 + col] = pack_h2(oacc[nt][0] * inv0, oacc[nt][1] * inv0);
        *(unsigned*)&o[r1 + col] = pack_h2(oacc[nt][2] * inv1, oacc[nt][3] * inv1);
    }
}

// ---------------- attention 2 via tf32 MMA: block per sb, 4 warps x 2 heads ------
// Reads xa [S,B,A,D] fp16; writes xf [A,B,S,D] as fp16 (fuses transpose).
#define H_STR 516
#define PW_STR 20
__global__ void __launch_bounds__(128) attn2_tc(const __half* __restrict__ xa,
                                                __half* __restrict__ o) {
    __shared__ unsigned hsu[16 * H_STR];
    __shared__ unsigned Pw2[4][16 * PW_STR];
    int sb = blockIdx.x;                      // s*16 + b
    int s_idx = sb >> 4, b_idx = sb & 15;
    int tid = threadIdx.x;
    int wid = tid >> 5, lane = tid & 31;
    int g = lane >> 2, tig = lane & 3;

    // load 16x512 fp16 tile, convert to tf32 words
    const uint4* src = (const uint4*)(xa + (size_t)sb * 16 * DD);  // 8 halfs each
#pragma unroll
    for (int i = 0; i < 8; i++) {
        int it = tid + 128 * i;               // 0..1023
        int r = it >> 6, c = it & 63;
        uint4 u = src[it];
        __half t[8];
        *(uint4*)t = u;
        uint4 w0 = make_uint4(f2tf32(__half2float(t[0])), f2tf32(__half2float(t[1])),
                              f2tf32(__half2float(t[2])), f2tf32(__half2float(t[3])));
        uint4 w1 = make_uint4(f2tf32(__half2float(t[4])), f2tf32(__half2float(t[5])),
                              f2tf32(__half2float(t[6])), f2tf32(__half2float(t[7])));
        *(uint4*)&hsu[r * H_STR + c * 8]     = w0;
        *(uint4*)&hsu[r * H_STR + c * 8 + 4] = w1;
    }
    __syncthreads();

    unsigned* ps = &Pw2[wid][0];
#pragma unroll
    for (int hh = 0; hh < 2; hh++) {
        int base = (wid * 2 + hh) * 64;

        float c[2][4];
#pragma unroll
        for (int nt = 0; nt < 2; nt++)
#pragma unroll
            for (int i = 0; i < 4; i++) c[nt][i] = 0.f;
#pragma unroll
        for (int kc = 0; kc < 8; kc++) {
            int kb = kc * 8;
            unsigned af[4];
            af[0] = hsu[g * H_STR + base + kb + tig];
            af[1] = hsu[(g + 8) * H_STR + base + kb + tig];
            af[2] = hsu[g * H_STR + base + kb + tig + 4];
            af[3] = hsu[(g + 8) * H_STR + base + kb + tig + 4];
#pragma unroll
            for (int nt = 0; nt < 2; nt++) {
                unsigned bf[2];
                bf[0] = hsu[(nt * 8 + g) * H_STR + base + kb + tig];
                bf[1] = hsu[(nt * 8 + g) * H_STR + base + kb + tig + 4];
                mma_tf32(c[nt], af, bf);
            }
        }

        float m0 = fmaxf(fmaxf(c[0][0], c[0][1]), fmaxf(c[1][0], c[1][1]));
        float m1 = fmaxf(fmaxf(c[0][2], c[0][3]), fmaxf(c[1][2], c[1][3]));
        m0 = fmaxf(m0, __shfl_xor_sync(0xffffffffu, m0, 1));
        m0 = fmaxf(m0, __shfl_xor_sync(0xffffffffu, m0, 2));
        m1 = fmaxf(m1, __shfl_xor_sync(0xffffffffu, m1, 1));
        m1 = fmaxf(m1, __shfl_xor_sync(0xffffffffu, m1, 2));
        float m0s = m0 * 0.125f, m1s = m1 * 0.125f;
        float e[2][4];
#pragma unroll
        for (int nt = 0; nt < 2; nt++) {
            e[nt][0] = __expf(c[nt][0] * 0.125f - m0s);
            e[nt][1] = __expf(c[nt][1] * 0.125f - m0s);
            e[nt][2] = __expf(c[nt][2] * 0.125f - m1s);
            e[nt][3] = __expf(c[nt][3] * 0.125f - m1s);
        }
        float s0 = e[0][0] + e[0][1] + e[1][0] + e[1][1];
        float s1 = e[0][2] + e[0][3] + e[1][2] + e[1][3];
        s0 += __shfl_xor_sync(0xffffffffu, s0, 1);
        s0 += __shfl_xor_sync(0xffffffffu, s0, 2);
        s1 += __shfl_xor_sync(0xffffffffu, s1, 1);
        s1 += __shfl_xor_sync(0xffffffffu, s1, 2);
        float inv0 = 1.f / s0, inv1 = 1.f / s1;

#pragma unroll
        for (int nt = 0; nt < 2; nt++) {
            int col = nt * 8 + 2 * tig;
            *(uint2*)&ps[g * PW_STR + col] =
                make_uint2(f2tf32(e[nt][0]), f2tf32(e[nt][1]));
            *(uint2*)&ps[(g + 8) * PW_STR + col] =
                make_uint2(f2tf32(e[nt][2]), f2tf32(e[nt][3]));
        }
        __syncwarp();

        float oc[8][4];
#pragma unroll
        for (int nt = 0; nt < 8; nt++)
#pragma unroll
            for (int i = 0; i < 4; i++) oc[nt][i] = 0.f;
#pragma unroll
        for (int kc = 0; kc < 2; kc++) {
            int kb = kc * 8;
            unsigned af[4];
            af[0] = ps[g * PW_STR + kb + tig];
            af[1] = ps[(g + 8) * PW_STR + kb + tig];
            af[2] = ps[g * PW_STR + kb + tig + 4];
            af[3] = ps[(g + 8) * PW_STR + kb + tig + 4];
#pragma unroll
            for (int nt = 0; nt < 8; nt++) {
                unsigned bf[2];
                bf[0] = hsu[(kb + tig) * H_STR + base + nt * 8 + g];
                bf[1] = hsu[(kb + tig + 4) * H_STR + base + nt * 8 + g];
                mma_tf32(oc[nt], af, bf);
            }
        }

        // dst row in [A,B,S,D]: (a*16+b)*128 + s ; fp16 output
        size_t r0 = ((size_t)((g * 16 + b_idx) * 128 + s_idx)) * 512 + base;
        size_t r1 = ((size_t)(((g + 8) * 16 + b_idx) * 128 + s_idx)) * 512 + base;
#pragma unroll
        for (int nt = 0; nt < 8; nt++) {
            int col = nt * 8 + 2 * tig;
            *(unsigned*)&o[r0 + col] = pack_h2(oc[nt][0] * inv0, oc[nt][1] * inv0);
            *(unsigned*)&o[r1 + col] = pack_h2(oc[nt][2] * inv1, oc[nt][3] * inv1);
        }
        __syncwarp();
    }
}

// =================================================================================
extern "C" void kernel_launch(void* const* d_in, const int* in_sizes, int n_in,
                              void* d_out, int out_size) {
    const float* query = (const float*)d_in[0];
    const float* key   = (const float*)d_in[1];
    const float* value = (const float*)d_in[2];
    // d_in[3] = mask (unused by reference)
    const float* padq  = (const float*)d_in[4];
    const float* padk  = (const float*)d_in[5];
    const float* Wq    = (const float*)d_in[6];
    const float* bq    = (const float*)d_in[7];
    const float* Wk    = (const float*)d_in[8];
    const float* bk    = (const float*)d_in[9];
    const float* Wv    = (const float*)d_in[10];
    const float* bv    = (const float*)d_in[11];
    const float* Wo    = (const float*)d_in[12];
    const float* bo    = (const float*)d_in[13];
    float* out = (float*)d_out;

    __half *xcq, *xck, *yqh, *ykh, *qh, *kh, *vh, *vh2, *xah, *xf, *Wh;
    float *wq, *wk;
    cudaGetSymbolAddress((void**)&xcq, g_xcq);
    cudaGetSymbolAddress((void**)&xck, g_xck);
    cudaGetSymbolAddress((void**)&yqh, g_yqh);
    cudaGetSymbolAddress((void**)&ykh, g_ykh);
    cudaGetSymbolAddress((void**)&wq,  g_wq);
    cudaGetSymbolAddress((void**)&wk,  g_wk);
    cudaGetSymbolAddress((void**)&qh,  g_qh);
    cudaGetSymbolAddress((void**)&kh,  g_kh);
    cudaGetSymbolAddress((void**)&vh,  g_vh);
    cudaGetSymbolAddress((void**)&vh2, g_vh2);
    cudaGetSymbolAddress((void**)&xah, g_xah);
    cudaGetSymbolAddress((void**)&xf,  g_xf);
    cudaGetSymbolAddress((void**)&Wh,  g_Wh);

    const size_t WSZ = (size_t)DD * DD;

    // --- input conversions (fp16) ---
    const int conc_blocks = (NN*SC*128) / 256;   // 16896
    k_concat_cvt<<<conc_blocks, 256>>>(query, padq, xcq);
    k_concat_cvt<<<conc_blocks, 256>>>(key,   padk, xck);
    k_cvt_h<<<(int)(WSZ/4 + 255)/256, 256>>>(Wq, Wh + 0*WSZ, (int)(WSZ/4));
    k_cvt_h<<<(int)(WSZ/4 + 255)/256, 256>>>(Wk, Wh + 1*WSZ, (int)(WSZ/4));
    k_cvt_h<<<(int)(WSZ/4 + 255)/256, 256>>>(Wv, Wh + 2*WSZ, (int)(WSZ/4));
    k_cvt_h<<<(int)(WSZ/4 + 255)/256, 256>>>(Wo, Wh + 3*WSZ, (int)(WSZ/4));
    k_cvt_h<<<(NN*SS*DD/4 + 255)/256, 256>>>(value, vh, NN*SS*DD/4);

    // --- projections (fp16 tensor-core, fp16 outputs for intermediates) ---
    const int gemm_smem = 2 * 2 * GSTG * 4;      // 73728 B
    cudaFuncSetAttribute(gemm_h<__half>, cudaFuncAttributeMaxDynamicSharedMemorySize, gemm_smem);
    cudaFuncSetAttribute(gemm_h<float>,  cudaFuncAttributeMaxDynamicSharedMemorySize, gemm_smem);
    dim3 gproj(DD/128, (NN*SC)/128);             // (4, 264)
    gemm_h<__half><<<gproj, 256, gemm_smem>>>(xcq, Wh + 0*WSZ, bq, yqh);
    gemm_h<__half><<<gproj, 256, gemm_smem>>>(xck, Wh + 1*WSZ, bk, ykh);
    dim3 gv(DD/128, (NN*SS)/128);                // (4, 256)
    gemm_h<__half><<<gv, 256, gemm_smem>>>(vh, Wh + 2*WSZ, bv, vh2);

    // --- local window reweighting (fp16 data) ---
    k_weights<<<(NN*SS)/4, 128>>>(yqh, wq);
    k_weights<<<(NN*SS)/4, 128>>>(ykh, wk);
    k_gather<<<NN*SS, 128>>>(yqh, wq, qh);
    k_gather<<<NN*SS, 128>>>(ykh, wk, kh);

    // --- attention 1 (fp16 MMA; fp16 in/out; writes [S,B,A,D]) ---
    const int attn1_smem = 27136 * 2;            // 54272 B
    cudaFuncSetAttribute(attn1_h, cudaFuncAttributeMaxDynamicSharedMemorySize, attn1_smem);
    attn1_h<<<NN*HH, 256, attn1_smem>>>(qh, kh, vh2, xah);

    // --- attention 2 (tf32 core; fp16 in/out; writes [A,B,S,D]) ---
    attn2_tc<<<SS*BB, 128>>>(xah, xf);

    // --- output projection (fp32 out) ---
    gemm_h<float><<<gv, 256, gemm_smem>>>(xf, Wh + 3*WSZ, bo, out);
}